// round 8
// baseline (speedup 1.0000x reference)
#include <cuda_runtime.h>
#include <math.h>

#define BSZn 32
#define SEQ 243
#define DIM 544
#define NH 8
#define HDIM 68
#define NSEED 17
#define UPD 1088
#define UC 136
#define MLP1 2176
#define MLP2 1088
#define TOK (BSZn*SEQ)          /* 7776 */
#define BHN (BSZn*NH*SEQ)       /* 62208 */

// ---------------- scratch (static device globals; no allocation) ----------------
__device__ float g_h[TOK*DIM];          // LN outputs
__device__ float g_qkv[TOK*3*DIM];      // qkv, later xu
__device__ float g_o[TOK*DIM];          // attention output
__device__ float g_big[TOK*MLP1];       // mlp hidden / o2 / emlp hidden
__device__ float g_a[BHN*NSEED];        // expert attention weights
__device__ float g_s0[NSEED*UPD];
__device__ float g_s1[NSEED*UPD];
__device__ float g_mean[NSEED];

// ======================= tf32 tensor-core GEMM =======================
// C[M,N] = A[M,K] * B[N,K]^T (+epilogue). K % 32 == 0.
// Block tile 128x128x32, 256 threads (8 warps, warp tile 32x64, mma m16n8k8).
// Double-buffered smem (dynamic): one __syncthreads per k-tile.
// EPI: 0 none, 1 +bias, 2 +bias+GELU(exact), 3 +bias+residual

#define GEMM_TILE_U (128 * 36)
#define GEMM_SMEM (4 * GEMM_TILE_U * (int)sizeof(unsigned))   /* 2 bufs x (A+B) */

__device__ __forceinline__ unsigned cvt_tf32(float x) {
    unsigned u;
    asm("cvt.rna.tf32.f32 %0, %1;" : "=r"(u) : "f"(x));
    return u;
}

__device__ __forceinline__ void mma_tf32(float* d, const unsigned* a, unsigned b0, unsigned b1) {
    asm volatile("mma.sync.aligned.m16n8k8.row.col.f32.tf32.tf32.f32 "
                 "{%0,%1,%2,%3}, {%4,%5,%6,%7}, {%8,%9}, {%0,%1,%2,%3};\n"
                 : "+f"(d[0]), "+f"(d[1]), "+f"(d[2]), "+f"(d[3])
                 : "r"(a[0]), "r"(a[1]), "r"(a[2]), "r"(a[3]), "r"(b0), "r"(b1));
}

template<int EPI>
__global__ __launch_bounds__(256)
void gemm_tf32_kernel(const float* __restrict__ A, const float* __restrict__ B,
                      const float* __restrict__ bias, const float* __restrict__ res,
                      float* __restrict__ C, int M, int Nn, int K) {
    extern __shared__ unsigned smem_u[];
    unsigned* Asb[2] = { smem_u,                  smem_u + 2 * GEMM_TILE_U };
    unsigned* Bsb[2] = { smem_u + GEMM_TILE_U,    smem_u + 3 * GEMM_TILE_U };

    const int tid  = threadIdx.x;
    const int warp = tid >> 5, lane = tid & 31;
    const int wm = (warp >> 1) * 32;    // warp row base (4 warps along M)
    const int wn = (warp & 1) * 64;     // warp col base (2 warps along N)
    const int q  = lane & 3;            // k quad
    const int rg = lane >> 2;           // row/col group 0..7
    const int m0 = blockIdx.y * 128, n0 = blockIdx.x * 128;

    // staging map: each thread loads 4 float4 per matrix
    const int lr = tid >> 3;            // base row 0..31 (stride 32)
    const int lc = (tid & 7) * 4;       // k offset 0..28

    float4 ra[4], rb[4];
    float acc[2][8][4];
#pragma unroll
    for (int i = 0; i < 2; i++)
#pragma unroll
        for (int j = 0; j < 8; j++)
#pragma unroll
            for (int c = 0; c < 4; c++) acc[i][j][c] = 0.f;

    const int T = K >> 5;

    auto load_t = [&](int t) {
        const int kb = t * 32 + lc;
#pragma unroll
        for (int p = 0; p < 4; p++) {
            int r = lr + p * 32;
            int ar = m0 + r;
            ra[p] = (ar < M) ? *(const float4*)(A + (size_t)ar * K + kb)
                             : make_float4(0.f, 0.f, 0.f, 0.f);
            int br = n0 + r;
            rb[p] = (br < Nn) ? *(const float4*)(B + (size_t)br * K + kb)
                              : make_float4(0.f, 0.f, 0.f, 0.f);
        }
    };
    auto store_t = [&](int buf) {
        unsigned* As = Asb[buf];
        unsigned* Bs = Bsb[buf];
#pragma unroll
        for (int p = 0; p < 4; p++) {
            int r = lr + p * 32;
            unsigned* da = &As[r * 36 + lc];
            da[0] = cvt_tf32(ra[p].x); da[1] = cvt_tf32(ra[p].y);
            da[2] = cvt_tf32(ra[p].z); da[3] = cvt_tf32(ra[p].w);
            unsigned* db = &Bs[r * 36 + lc];
            db[0] = cvt_tf32(rb[p].x); db[1] = cvt_tf32(rb[p].y);
            db[2] = cvt_tf32(rb[p].z); db[3] = cvt_tf32(rb[p].w);
        }
    };

    load_t(0);
    store_t(0);
    __syncthreads();

    for (int t = 0; t < T; t++) {
        if (t + 1 < T) load_t(t + 1);   // global prefetch overlaps compute
        const unsigned* As = Asb[t & 1];
        const unsigned* Bs = Bsb[t & 1];

#pragma unroll
        for (int s = 0; s < 4; s++) {
            const int k0 = s * 8;
            unsigned afr[2][4];
#pragma unroll
            for (int mt = 0; mt < 2; mt++) {
                int r = wm + mt * 16 + rg;
                afr[mt][0] = As[r * 36 + k0 + q];
                afr[mt][1] = As[(r + 8) * 36 + k0 + q];
                afr[mt][2] = As[r * 36 + k0 + q + 4];
                afr[mt][3] = As[(r + 8) * 36 + k0 + q + 4];
            }
#pragma unroll
            for (int nt = 0; nt < 8; nt++) {
                int cb = wn + nt * 8 + rg;
                unsigned b0 = Bs[cb * 36 + k0 + q];
                unsigned b1 = Bs[cb * 36 + k0 + q + 4];
                mma_tf32(acc[0][nt], afr[0], b0, b1);
                mma_tf32(acc[1][nt], afr[1], b0, b1);
            }
        }

        if (t + 1 < T) {
            store_t((t + 1) & 1);   // writes other buffer: safe vs. warps still computing
            __syncthreads();        // visible before next tile's compute
        }
    }

    // epilogue
#pragma unroll
    for (int mt = 0; mt < 2; mt++)
#pragma unroll
        for (int half = 0; half < 2; half++) {
            int row = m0 + wm + mt * 16 + rg + half * 8;
            if (row >= M) continue;
#pragma unroll
            for (int nt = 0; nt < 8; nt++) {
                int col = n0 + wn + nt * 8 + 2 * q;
                if (col >= Nn) continue;
                float v0 = acc[mt][nt][half * 2 + 0];
                float v1 = acc[mt][nt][half * 2 + 1];
                if (EPI >= 1) { v0 += bias[col]; v1 += bias[col + 1]; }
                if (EPI == 2) {
                    v0 = 0.5f * v0 * (1.0f + erff(v0 * 0.70710678118654752f));
                    v1 = 0.5f * v1 * (1.0f + erff(v1 * 0.70710678118654752f));
                }
                size_t idx = (size_t)row * Nn + col;
                if (EPI == 3) { v0 += res[idx]; v1 += res[idx + 1]; }
                C[idx] = v0; C[idx + 1] = v1;
            }
        }
}

// ---------------- FFMA SGEMM (tiny seed GEMMs only) ----------------
template<int EPI>
__global__ void gemm_kernel(const float* __restrict__ A, const float* __restrict__ B,
                            const float* __restrict__ bias, const float* __restrict__ res,
                            float* __restrict__ C, int M, int Nn, int K) {
    __shared__ float As[16][64];
    __shared__ float Bs[16][64];
    const int tid = threadIdx.x;
    const int m0 = blockIdx.y * 64;
    const int n0 = blockIdx.x * 64;
    const int ty = tid >> 4;
    const int tx = tid & 15;
    const int lm = tid >> 2;
    const int lk = (tid & 3) * 4;

    float acc[4][4];
#pragma unroll
    for (int i = 0; i < 4; i++)
#pragma unroll
        for (int j = 0; j < 4; j++) acc[i][j] = 0.f;

    for (int k0 = 0; k0 < K; k0 += 16) {
        float4 a4 = make_float4(0.f, 0.f, 0.f, 0.f);
        int ar = m0 + lm;
        if (ar < M) a4 = *(const float4*)(A + (size_t)ar * K + k0 + lk);
        As[lk + 0][lm] = a4.x; As[lk + 1][lm] = a4.y;
        As[lk + 2][lm] = a4.z; As[lk + 3][lm] = a4.w;

        float4 b4 = make_float4(0.f, 0.f, 0.f, 0.f);
        int br = n0 + lm;
        if (br < Nn) b4 = *(const float4*)(B + (size_t)br * K + k0 + lk);
        Bs[lk + 0][lm] = b4.x; Bs[lk + 1][lm] = b4.y;
        Bs[lk + 2][lm] = b4.z; Bs[lk + 3][lm] = b4.w;
        __syncthreads();

#pragma unroll
        for (int kk = 0; kk < 16; kk++) {
            float4 av = *(const float4*)(&As[kk][ty * 4]);
            float4 bv = *(const float4*)(&Bs[kk][tx * 4]);
            float am[4] = {av.x, av.y, av.z, av.w};
            float bn[4] = {bv.x, bv.y, bv.z, bv.w};
#pragma unroll
            for (int i = 0; i < 4; i++)
#pragma unroll
                for (int j = 0; j < 4; j++) acc[i][j] = fmaf(am[i], bn[j], acc[i][j]);
        }
        __syncthreads();
    }

#pragma unroll
    for (int i = 0; i < 4; i++) {
        int row = m0 + ty * 4 + i;
        if (row >= M) continue;
#pragma unroll
        for (int j = 0; j < 4; j++) {
            int col = n0 + tx * 4 + j;
            if (col >= Nn) continue;
            float v = acc[i][j];
            if (EPI >= 1) v += bias[col];
            if (EPI == 2) v = 0.5f * v * (1.0f + erff(v * 0.70710678118654752f));
            if (EPI == 3) v += res[(size_t)row * Nn + col];
            C[(size_t)row * Nn + col] = v;
        }
    }
}

// ---------------- LayerNorm over DIM per token ----------------
__global__ void ln_kernel(const float* __restrict__ x, const float* __restrict__ g,
                          const float* __restrict__ b, float* __restrict__ y) {
    const int t = blockIdx.x;
    const int tid = threadIdx.x;                 // 256 threads
    const float* xr = x + (size_t)t * DIM;
    float v[3];
    float s = 0.f, s2 = 0.f;
    int cnt = 0;
    for (int c = tid; c < DIM; c += 256) { float val = xr[c]; v[cnt++] = val; s += val; s2 += val * val; }
    __shared__ float shs[8], shs2[8];
    for (int off = 16; off; off >>= 1) { s += __shfl_xor_sync(~0u, s, off); s2 += __shfl_xor_sync(~0u, s2, off); }
    int lane = tid & 31, w = tid >> 5;
    if (lane == 0) { shs[w] = s; shs2[w] = s2; }
    __syncthreads();
    float S = 0.f, S2 = 0.f;
    for (int i = 0; i < 8; i++) { S += shs[i]; S2 += shs2[i]; }
    const float mean = S / (float)DIM;
    const float var = S2 / (float)DIM - mean * mean;
    const float inv = rsqrtf(var + 1e-5f);
    cnt = 0;
    for (int c = tid; c < DIM; c += 256)
        y[(size_t)t * DIM + c] = (v[cnt++] - mean) * inv * g[c] + b[c];
}

// ---------------- Attention v4: block per (b,h), warp x 4 queries, K/V reuse ----------------
#define KPAD 76                        /* conflict-free pitch: 76 mod 32 = 12 */
#define NW3 16                         /* warps per block */
#define IQ 4                           /* queries per warp pass */
#define PPITCH 244                     /* prob row pitch (mult of 4) */

__global__ __launch_bounds__(512)
void attn4_kernel(const float* __restrict__ qkv, const float* __restrict__ btab,
                  float* __restrict__ o) {
    extern __shared__ float sh[];
    float* k_sh    = sh;                           // [SEQ*KPAD]
    float* v_sh    = k_sh + SEQ * KPAD;            // [SEQ*KPAD]
    float* p_sh    = v_sh + SEQ * KPAD;            // [NW3*IQ*PPITCH]
    float* q_sh    = p_sh + NW3 * IQ * PPITCH;     // [NW3*IQ*HDIM]
    float* bias_sh = q_sh + NW3 * IQ * HDIM;       // [2*SEQ-1]

    const int bh = blockIdx.x;
    const int h = bh % NH;
    const int b = bh / NH;
    const int tid = threadIdx.x;
    const int lane = tid & 31, w = tid >> 5;

    // block preload: k, v, bias
    for (int idx = tid; idx < SEQ * HDIM; idx += 512) {
        int j = idx / HDIM, c = idx % HDIM;
        size_t base = ((size_t)(b * SEQ + j) * 3) * DIM + h * HDIM + c;
        k_sh[j * KPAD + c] = qkv[base + DIM];
        v_sh[j * KPAD + c] = qkv[base + 2 * DIM];
    }
    for (int idx = tid; idx < 2 * SEQ - 1; idx += 512)
        bias_sh[idx] = btab[h * (2 * SEQ - 1) + idx];
    __syncthreads();            // the only block barrier

    const float scale = rsqrtf((float)HDIM);
    float* q_w  = q_sh + w * IQ * HDIM;
    float* p_w0 = p_sh + w * IQ * PPITCH;

    int jj[8], koff[8];
#pragma unroll
    for (int t = 0; t < 8; t++) {
        int j = lane + 32 * t;
        jj[t] = j;
        koff[t] = (j < SEQ ? j : SEQ - 1) * KPAD;
    }

    const int c2 = 2 * lane;
    const bool xtra = (lane < 2);
    const int cx = 64 + 2 * lane;

    for (int g = w; g * IQ < SEQ; g += NW3) {
        const int i0 = g * IQ;

        // warp-private q tile load (each query read once per block total)
        for (int idx = lane; idx < IQ * HDIM; idx += 32) {
            int qi = idx / HDIM, c = idx - qi * HDIM;
            int i = i0 + qi;
            q_w[idx] = (i < SEQ) ? qkv[((size_t)(b * SEQ + i) * 3) * DIM + h * HDIM + c] : 0.f;
        }
        __syncwarp();

        // ---- scores: k4 loads shared across IQ queries ----
        float sc[IQ][8];
#pragma unroll
        for (int qi = 0; qi < IQ; qi++)
#pragma unroll
            for (int t = 0; t < 8; t++) sc[qi][t] = 0.f;

#pragma unroll
        for (int c4 = 0; c4 < HDIM / 4; c4++) {
            float4 q4[IQ];
#pragma unroll
            for (int qi = 0; qi < IQ; qi++)
                q4[qi] = ((const float4*)(q_w + qi * HDIM))[c4];
#pragma unroll
            for (int t = 0; t < 8; t++) {
                float4 k4 = *(const float4*)(k_sh + koff[t] + 4 * c4);
#pragma unroll
                for (int qi = 0; qi < IQ; qi++) {
                    sc[qi][t] = fmaf(q4[qi].x, k4.x, sc[qi][t]);
                    sc[qi][t] = fmaf(q4[qi].y, k4.y, sc[qi][t]);
                    sc[qi][t] = fmaf(q4[qi].z, k4.z, sc[qi][t]);
                    sc[qi][t] = fmaf(q4[qi].w, k4.w, sc[qi][t]);
                }
            }
        }

        // ---- per-query softmax (warp shuffles) + prob writes ----
#pragma unroll
        for (int qi = 0; qi < IQ; qi++) {
            const int i = i0 + qi;
            const bool qv = (i < SEQ);
            float* p_w = p_w0 + qi * PPITCH;
            float mx = -1e30f;
#pragma unroll
            for (int t = 0; t < 8; t++) {
                if (qv && jj[t] < SEQ) {
                    sc[qi][t] = sc[qi][t] * scale + bias_sh[i - jj[t] + SEQ - 1];
                    mx = fmaxf(mx, sc[qi][t]);
                } else sc[qi][t] = -1e30f;
            }
#pragma unroll
            for (int off = 16; off; off >>= 1) mx = fmaxf(mx, __shfl_xor_sync(~0u, mx, off));
            float sum = 0.f;
#pragma unroll
            for (int t = 0; t < 8; t++) {
                float e = (qv && jj[t] < SEQ) ? __expf(sc[qi][t] - mx) : 0.f;
                sc[qi][t] = e;
                sum += e;
            }
#pragma unroll
            for (int off = 16; off; off >>= 1) sum += __shfl_xor_sync(~0u, sum, off);
            const float invS = qv ? (1.f / sum) : 0.f;
#pragma unroll
            for (int t = 0; t < 8; t++)
                if (jj[t] < PPITCH) p_w[jj[t]] = sc[qi][t] * invS;   // j=243 gets 0
        }
        __syncwarp();

        // ---- PV: v2 loads shared across IQ queries, probs as float4 broadcast ----
        float acc[IQ][2], accx[IQ][2];
#pragma unroll
        for (int qi = 0; qi < IQ; qi++) {
            acc[qi][0] = acc[qi][1] = 0.f;
            accx[qi][0] = accx[qi][1] = 0.f;
        }

#define PV_STEP(COMP, JOFF)                                                    \
        {                                                                      \
            const float* vrow = v_sh + (j4 + (JOFF)) * KPAD;                   \
            float2 v2 = *(const float2*)(vrow + c2);                           \
            _Pragma("unroll")                                                  \
            for (int qi = 0; qi < IQ; qi++) {                                  \
                acc[qi][0] = fmaf(P[qi].COMP, v2.x, acc[qi][0]);               \
                acc[qi][1] = fmaf(P[qi].COMP, v2.y, acc[qi][1]);               \
            }                                                                  \
            if (xtra) {                                                        \
                float2 vx = *(const float2*)(vrow + cx);                       \
                _Pragma("unroll")                                              \
                for (int qi = 0; qi < IQ; qi++) {                              \
                    accx[qi][0] = fmaf(P[qi].COMP, vx.x, accx[qi][0]);         \
                    accx[qi][1] = fmaf(P[qi].COMP, vx.y, accx[qi][1]);         \
                }                                                              \
            }                                                                  \
        }

#pragma unroll 1
        for (int j4 = 0; j4 < 240; j4 += 4) {
            float4 P[IQ];
#pragma unroll
            for (int qi = 0; qi < IQ; qi++)
                P[qi] = *(const float4*)(p_w0 + qi * PPITCH + j4);
            PV_STEP(x, 0)
            PV_STEP(y, 1)
            PV_STEP(z, 2)
            PV_STEP(w, 3)
        }
        // tail j = 240..242
        for (int j = 240; j < SEQ; j++) {
            const float* vrow = v_sh + j * KPAD;
            float2 v2 = *(const float2*)(vrow + c2);
#pragma unroll
            for (int qi = 0; qi < IQ; qi++) {
                float p = p_w0[qi * PPITCH + j];
                acc[qi][0] = fmaf(p, v2.x, acc[qi][0]);
                acc[qi][1] = fmaf(p, v2.y, acc[qi][1]);
            }
            if (xtra) {
                float2 vx = *(const float2*)(vrow + cx);
#pragma unroll
                for (int qi = 0; qi < IQ; qi++) {
                    float p = p_w0[qi * PPITCH + j];
                    accx[qi][0] = fmaf(p, vx.x, accx[qi][0]);
                    accx[qi][1] = fmaf(p, vx.y, accx[qi][1]);
                }
            }
        }
#undef PV_STEP

        // ---- write outputs ----
#pragma unroll
        for (int qi = 0; qi < IQ; qi++) {
            int i = i0 + qi;
            if (i >= SEQ) break;
            float* orow = o + (size_t)(b * SEQ + i) * DIM + h * HDIM;
            orow[c2] = acc[qi][0];
            orow[c2 + 1] = acc[qi][1];
            if (xtra) { orow[cx] = accx[qi][0]; orow[cx + 1] = accx[qi][1]; }
        }
        __syncwarp();
    }
}

#define ATTN4_SMEM ((2*SEQ*KPAD + NW3*IQ*PPITCH + NW3*IQ*HDIM + (2*SEQ-1)) * (int)sizeof(float))

// ---------------- expert logits: warp per (b,h,f) ----------------
__global__ void expert_logits_kernel(const float* __restrict__ xu, const float* __restrict__ s0,
                                     float* __restrict__ a) {
    const int gw = (blockIdx.x * blockDim.x + threadIdx.x) >> 5;
    if (gw >= BHN) return;
    const int lane = threadIdx.x & 31;
    const int f = gw % SEQ;
    const int h = (gw / SEQ) % NH;
    const int b = gw / (SEQ * NH);
    const float* xr = xu + (size_t)(b * SEQ + f) * UPD + h * UC;
    float xv[5];
#pragma unroll
    for (int q = 0; q < 5; q++) { int c = lane + 32 * q; xv[q] = (c < UC) ? xr[c] : 0.f; }
    const float* s0h = s0 + h * UC;
    float* ar = a + (size_t)gw * NSEED;
    for (int n = 0; n < NSEED; n++) {
        const float* sr = s0h + (size_t)n * UPD;
        float p = 0.f;
#pragma unroll
        for (int q = 0; q < 5; q++) { int c = lane + 32 * q; if (c < UC) p += xv[q] * sr[c]; }
        for (int off = 16; off; off >>= 1) p += __shfl_xor_sync(~0u, p, off);
        if (lane == 0) ar[n] = p;
    }
}

// ---------------- softmax over f (axis=-2): block per (b,h,n) ----------------
__global__ void softmax_f_kernel(float* __restrict__ a) {
    const int idx = blockIdx.x;            // b*H*NS + h*NS + n
    const int n = idx % NSEED;
    const int bh = idx / NSEED;
    float* base = a + (size_t)bh * SEQ * NSEED + n;
    const int tid = threadIdx.x;           // 256
    __shared__ float redm[8], redsum[8], bcast[2];
    const int lane = tid & 31, w = tid >> 5;
    float v = (tid < SEQ) ? base[(size_t)tid * NSEED] : -1e30f;
    float m = v;
    for (int off = 16; off; off >>= 1) m = fmaxf(m, __shfl_xor_sync(~0u, m, off));
    if (lane == 0) redm[w] = m;
    __syncthreads();
    if (tid == 0) {
        float mm = redm[0];
        for (int k = 1; k < 8; k++) mm = fmaxf(mm, redm[k]);
        bcast[0] = mm;
    }
    __syncthreads();
    const float M = bcast[0];
    float e = (tid < SEQ) ? __expf(v - M) : 0.f;
    float s = e;
    for (int off = 16; off; off >>= 1) s += __shfl_xor_sync(~0u, s, off);
    if (lane == 0) redsum[w] = s;
    __syncthreads();
    if (tid == 0) {
        float ss = 0.f;
        for (int k = 0; k < 8; k++) ss += redsum[k];
        bcast[1] = 1.f / ss;
    }
    __syncthreads();
    if (tid < SEQ) base[(size_t)tid * NSEED] = e * bcast[1];
}

// ---------------- normalize over n, accumulate mean, produce o2 ----------------
__global__ void expert_out_kernel(const float* __restrict__ a, const float* __restrict__ s1,
                                  float* __restrict__ o2, float* __restrict__ mean_acc) {
    const int gw = blockIdx.x;             // (b,h,f)
    const int f = gw % SEQ;
    const int h = (gw / SEQ) % NH;
    const int b = gw / (SEQ * NH);
    __shared__ float a_sh[NSEED];
    __shared__ float inv_s;
    const int tid = threadIdx.x;           // 160
    if (tid < NSEED) a_sh[tid] = a[(size_t)gw * NSEED + tid];
    __syncthreads();
    if (tid == 0) {
        float s = 0.f;
        for (int n = 0; n < NSEED; n++) s += a_sh[n];
        inv_s = 1.f / (1e-7f + s);
    }
    __syncthreads();
    if (tid < NSEED) {
        float val = a_sh[tid] * inv_s;
        a_sh[tid] = val;
        atomicAdd(mean_acc + tid, val);
    }
    __syncthreads();
    if (tid < UC) {
        const float* s1h = s1 + h * UC + tid;
        float acc = 0.f;
#pragma unroll
        for (int n = 0; n < NSEED; n++) acc += a_sh[n] * s1h[(size_t)n * UPD];
        o2[(size_t)(b * SEQ + f) * UPD + h * UC + tid] = acc;
    }
}

__global__ void zero_mean_kernel(float* __restrict__ mean_acc) {
    if (threadIdx.x < NSEED) mean_acc[threadIdx.x] = 0.f;
}

__global__ void finalize_mean_kernel(const float* __restrict__ mean_acc, float* __restrict__ out) {
    if (threadIdx.x < NSEED)
        out[threadIdx.x] = mean_acc[threadIdx.x] * (1.0f / (float)BHN);
}

// ---------------- driver ----------------
static inline dim3 gemm_grid64(int M, int Nn) { return dim3((Nn + 63) / 64, (M + 63) / 64); }
static inline dim3 gemm_grid128(int M, int Nn) { return dim3((Nn + 127) / 128, (M + 127) / 128); }

extern "C" void kernel_launch(void* const* d_in, const int* in_sizes, int n_in,
                              void* d_out, int out_size) {
    const float* x      = (const float*)d_in[0];
    const float* seed   = (const float*)d_in[1];
    const float* ln1_g  = (const float*)d_in[2];
    const float* ln1_b  = (const float*)d_in[3];
    const float* w_qkv  = (const float*)d_in[4];
    const float* w_proj = (const float*)d_in[5];
    const float* b_proj = (const float*)d_in[6];
    const float* b_tab  = (const float*)d_in[7];
    const float* ln2_g  = (const float*)d_in[8];
    const float* ln2_b  = (const float*)d_in[9];
    const float* mlp_w1 = (const float*)d_in[10];
    const float* mlp_b1 = (const float*)d_in[11];
    const float* mlp_w2 = (const float*)d_in[12];
    const float* mlp_b2 = (const float*)d_in[13];
    const float* eln1_g = (const float*)d_in[14];
    const float* eln1_b = (const float*)d_in[15];
    const float* w_trans= (const float*)d_in[16];
    const float* b_trans= (const float*)d_in[17];
    const float* w0     = (const float*)d_in[18];
    const float* b0     = (const float*)d_in[19];
    const float* w1     = (const float*)d_in[20];
    const float* b1     = (const float*)d_in[21];
    const float* w_proj2= (const float*)d_in[22];
    const float* b_proj2= (const float*)d_in[23];
    const float* eln2_g = (const float*)d_in[24];
    const float* eln2_b = (const float*)d_in[25];
    const float* emlp_w1= (const float*)d_in[26];
    const float* emlp_b1= (const float*)d_in[27];
    const float* emlp_w2= (const float*)d_in[28];
    const float* emlp_b2= (const float*)d_in[29];

    float* xbuf = (float*)d_out;                  // running x lives in d_out
    float* out_mean = (float*)d_out + (size_t)TOK * DIM;

    float *p_h, *p_qkv, *p_o, *p_big, *p_a, *p_s0, *p_s1, *p_mean;
    cudaGetSymbolAddress((void**)&p_h,   g_h);
    cudaGetSymbolAddress((void**)&p_qkv, g_qkv);
    cudaGetSymbolAddress((void**)&p_o,   g_o);
    cudaGetSymbolAddress((void**)&p_big, g_big);
    cudaGetSymbolAddress((void**)&p_a,   g_a);
    cudaGetSymbolAddress((void**)&p_s0,  g_s0);
    cudaGetSymbolAddress((void**)&p_s1,  g_s1);
    cudaGetSymbolAddress((void**)&p_mean,g_mean);

    cudaFuncSetAttribute(attn4_kernel, cudaFuncAttributeMaxDynamicSharedMemorySize, ATTN4_SMEM);
    cudaFuncSetAttribute(gemm_tf32_kernel<0>, cudaFuncAttributeMaxDynamicSharedMemorySize, GEMM_SMEM);
    cudaFuncSetAttribute(gemm_tf32_kernel<1>, cudaFuncAttributeMaxDynamicSharedMemorySize, GEMM_SMEM);
    cudaFuncSetAttribute(gemm_tf32_kernel<2>, cudaFuncAttributeMaxDynamicSharedMemorySize, GEMM_SMEM);
    cudaFuncSetAttribute(gemm_tf32_kernel<3>, cudaFuncAttributeMaxDynamicSharedMemorySize, GEMM_SMEM);

    // x -> output buffer (running residual stream)
    cudaMemcpyAsync(xbuf, x, (size_t)TOK * DIM * sizeof(float), cudaMemcpyDeviceToDevice);
    zero_mean_kernel<<<1, 32>>>(p_mean);

    // ---- block 1: attention ----
    ln_kernel<<<TOK, 256>>>(xbuf, ln1_g, ln1_b, p_h);
    gemm_tf32_kernel<0><<<gemm_grid128(TOK, 3 * DIM), 256, GEMM_SMEM>>>(p_h, w_qkv, nullptr, nullptr, p_qkv, TOK, 3 * DIM, DIM);
    attn4_kernel<<<BSZn * NH, 512, ATTN4_SMEM>>>(p_qkv, b_tab, p_o);
    gemm_tf32_kernel<3><<<gemm_grid128(TOK, DIM), 256, GEMM_SMEM>>>(p_o, w_proj, b_proj, xbuf, xbuf, TOK, DIM, DIM);

    // ---- block 2: MLP ----
    ln_kernel<<<TOK, 256>>>(xbuf, ln2_g, ln2_b, p_h);
    gemm_tf32_kernel<2><<<gemm_grid128(TOK, MLP1), 256, GEMM_SMEM>>>(p_h, mlp_w1, mlp_b1, nullptr, p_big, TOK, MLP1, DIM);
    gemm_tf32_kernel<3><<<gemm_grid128(TOK, DIM), 256, GEMM_SMEM>>>(p_big, mlp_w2, mlp_b2, xbuf, xbuf, TOK, DIM, MLP1);

    // ---- block 3: seed-expert attention ----
    ln_kernel<<<TOK, 256>>>(xbuf, eln1_g, eln1_b, p_h);
    gemm_tf32_kernel<1><<<gemm_grid128(TOK, UPD), 256, GEMM_SMEM>>>(p_h, w_trans, b_trans, nullptr, p_qkv, TOK, UPD, DIM);
    gemm_kernel<1><<<gemm_grid64(NSEED, UPD), 256>>>(seed, w0, b0, nullptr, p_s0, NSEED, UPD, DIM);
    gemm_kernel<1><<<gemm_grid64(NSEED, UPD), 256>>>(seed, w1, b1, nullptr, p_s1, NSEED, UPD, DIM);
    expert_logits_kernel<<<(BHN * 32 + 127) / 128, 128>>>(p_qkv, p_s0, p_a);
    softmax_f_kernel<<<BSZn * NH * NSEED, 256>>>(p_a);
    expert_out_kernel<<<BHN, 160>>>(p_a, p_s1, p_big, p_mean);
    finalize_mean_kernel<<<1, 32>>>(p_mean, out_mean);
    gemm_tf32_kernel<3><<<gemm_grid128(TOK, DIM), 256, GEMM_SMEM>>>(p_big, w_proj2, b_proj2, xbuf, xbuf, TOK, DIM, UPD);

    // ---- block 4: expert MLP ----
    ln_kernel<<<TOK, 256>>>(xbuf, eln2_g, eln2_b, p_h);
    gemm_tf32_kernel<2><<<gemm_grid128(TOK, MLP2), 256, GEMM_SMEM>>>(p_h, emlp_w1, emlp_b1, nullptr, p_big, TOK, MLP2, DIM);
    gemm_tf32_kernel<3><<<gemm_grid128(TOK, DIM), 256, GEMM_SMEM>>>(p_big, emlp_w2, emlp_b2, xbuf, xbuf, TOK, DIM, MLP2);
}

// round 10
// speedup vs baseline: 1.2632x; 1.2632x over previous
#include <cuda_runtime.h>
#include <math.h>

#define BSZn 32
#define SEQ 243
#define DIM 544
#define NH 8
#define HDIM 68
#define NSEED 17
#define UPD 1088
#define UC 136
#define MLP1 2176
#define MLP2 1088
#define TOK (BSZn*SEQ)          /* 7776 */
#define BHN (BSZn*NH*SEQ)       /* 62208 */

// ---------------- scratch (static device globals; no allocation) ----------------
__device__ float g_h[TOK*DIM];          // LN outputs
__device__ float g_qkv[TOK*3*DIM];      // qkv, later xu
__device__ float g_o[TOK*DIM];          // attention output
__device__ float g_big[TOK*MLP1];       // mlp hidden / o2 / emlp hidden
__device__ float g_a[BHN*NSEED];        // expert attention weights
__device__ float g_s0[NSEED*UPD];
__device__ float g_s1[NSEED*UPD];
__device__ float g_mean[NSEED];

// ======================= tf32 tensor-core GEMM =======================
// C[M,N] = A[M,K] * B[N,K]^T (+epilogue). K % 32 == 0.
// Block tile 128x128x32, 256 threads (8 warps, warp tile 32x64, mma m16n8k8).
// Single-buffer static smem (R7 measured-good version).
// EPI: 0 none, 1 +bias, 2 +bias+GELU(exact), 3 +bias+residual

__device__ __forceinline__ unsigned cvt_tf32(float x) {
    unsigned u;
    asm("cvt.rna.tf32.f32 %0, %1;" : "=r"(u) : "f"(x));
    return u;
}

__device__ __forceinline__ void mma_tf32(float* d, const unsigned* a, unsigned b0, unsigned b1) {
    asm volatile("mma.sync.aligned.m16n8k8.row.col.f32.tf32.tf32.f32 "
                 "{%0,%1,%2,%3}, {%4,%5,%6,%7}, {%8,%9}, {%0,%1,%2,%3};\n"
                 : "+f"(d[0]), "+f"(d[1]), "+f"(d[2]), "+f"(d[3])
                 : "r"(a[0]), "r"(a[1]), "r"(a[2]), "r"(a[3]), "r"(b0), "r"(b1));
}

template<int EPI>
__global__ __launch_bounds__(256)
void gemm_tf32_kernel(const float* __restrict__ A, const float* __restrict__ B,
                      const float* __restrict__ bias, const float* __restrict__ res,
                      float* __restrict__ C, int M, int Nn, int K) {
    __shared__ unsigned As[128 * 36];   // [row][k], pad 36 -> conflict-free frag loads
    __shared__ unsigned Bs[128 * 36];   // [col(n)][k]
    const int tid  = threadIdx.x;
    const int warp = tid >> 5, lane = tid & 31;
    const int wm = (warp >> 1) * 32;    // warp row base (4 warps along M)
    const int wn = (warp & 1) * 64;     // warp col base (2 warps along N)
    const int q  = lane & 3;            // k quad
    const int rg = lane >> 2;           // row/col group 0..7
    const int m0 = blockIdx.y * 128, n0 = blockIdx.x * 128;

    // staging map: each thread loads 4 float4 per matrix
    const int lr = tid >> 3;            // base row 0..31 (stride 32)
    const int lc = (tid & 7) * 4;       // k offset 0..28

    float4 ra[4], rb[4];
    float acc[2][8][4];
#pragma unroll
    for (int i = 0; i < 2; i++)
#pragma unroll
        for (int j = 0; j < 8; j++)
#pragma unroll
            for (int c = 0; c < 4; c++) acc[i][j][c] = 0.f;

    const int T = K >> 5;

    // load tile t into registers
    auto load_t = [&](int t) {
        const int kb = t * 32 + lc;
#pragma unroll
        for (int p = 0; p < 4; p++) {
            int r = lr + p * 32;
            int ar = m0 + r;
            ra[p] = (ar < M) ? *(const float4*)(A + (size_t)ar * K + kb)
                             : make_float4(0.f, 0.f, 0.f, 0.f);
            int br = n0 + r;
            rb[p] = (br < Nn) ? *(const float4*)(B + (size_t)br * K + kb)
                              : make_float4(0.f, 0.f, 0.f, 0.f);
        }
    };
    // convert + store registers into smem
    auto store_t = [&]() {
#pragma unroll
        for (int p = 0; p < 4; p++) {
            int r = lr + p * 32;
            unsigned* da = &As[r * 36 + lc];
            da[0] = cvt_tf32(ra[p].x); da[1] = cvt_tf32(ra[p].y);
            da[2] = cvt_tf32(ra[p].z); da[3] = cvt_tf32(ra[p].w);
            unsigned* db = &Bs[r * 36 + lc];
            db[0] = cvt_tf32(rb[p].x); db[1] = cvt_tf32(rb[p].y);
            db[2] = cvt_tf32(rb[p].z); db[3] = cvt_tf32(rb[p].w);
        }
    };

    load_t(0);
    store_t();
    __syncthreads();

    for (int t = 0; t < T; t++) {
        if (t + 1 < T) load_t(t + 1);   // global prefetch overlaps compute

#pragma unroll
        for (int s = 0; s < 4; s++) {
            const int k0 = s * 8;
            unsigned afr[2][4];
#pragma unroll
            for (int mt = 0; mt < 2; mt++) {
                int r = wm + mt * 16 + rg;
                afr[mt][0] = As[r * 36 + k0 + q];
                afr[mt][1] = As[(r + 8) * 36 + k0 + q];
                afr[mt][2] = As[r * 36 + k0 + q + 4];
                afr[mt][3] = As[(r + 8) * 36 + k0 + q + 4];
            }
#pragma unroll
            for (int nt = 0; nt < 8; nt++) {
                int cb = wn + nt * 8 + rg;
                unsigned b0 = Bs[cb * 36 + k0 + q];
                unsigned b1 = Bs[cb * 36 + k0 + q + 4];
                mma_tf32(acc[0][nt], afr[0], b0, b1);
                mma_tf32(acc[1][nt], afr[1], b0, b1);
            }
        }

        if (t + 1 < T) {
            __syncthreads();   // all warps done reading smem
            store_t();
            __syncthreads();   // stores visible
        }
    }

    // epilogue
#pragma unroll
    for (int mt = 0; mt < 2; mt++)
#pragma unroll
        for (int half = 0; half < 2; half++) {
            int row = m0 + wm + mt * 16 + rg + half * 8;
            if (row >= M) continue;
#pragma unroll
            for (int nt = 0; nt < 8; nt++) {
                int col = n0 + wn + nt * 8 + 2 * q;
                if (col >= Nn) continue;
                float v0 = acc[mt][nt][half * 2 + 0];
                float v1 = acc[mt][nt][half * 2 + 1];
                if (EPI >= 1) { v0 += bias[col]; v1 += bias[col + 1]; }
                if (EPI == 2) {
                    v0 = 0.5f * v0 * (1.0f + erff(v0 * 0.70710678118654752f));
                    v1 = 0.5f * v1 * (1.0f + erff(v1 * 0.70710678118654752f));
                }
                size_t idx = (size_t)row * Nn + col;
                if (EPI == 3) { v0 += res[idx]; v1 += res[idx + 1]; }
                C[idx] = v0; C[idx + 1] = v1;
            }
        }
}

// ---------------- FFMA SGEMM (tiny seed GEMMs only) ----------------
template<int EPI>
__global__ void gemm_kernel(const float* __restrict__ A, const float* __restrict__ B,
                            const float* __restrict__ bias, const float* __restrict__ res,
                            float* __restrict__ C, int M, int Nn, int K) {
    __shared__ float As[16][64];
    __shared__ float Bs[16][64];
    const int tid = threadIdx.x;
    const int m0 = blockIdx.y * 64;
    const int n0 = blockIdx.x * 64;
    const int ty = tid >> 4;
    const int tx = tid & 15;
    const int lm = tid >> 2;
    const int lk = (tid & 3) * 4;

    float acc[4][4];
#pragma unroll
    for (int i = 0; i < 4; i++)
#pragma unroll
        for (int j = 0; j < 4; j++) acc[i][j] = 0.f;

    for (int k0 = 0; k0 < K; k0 += 16) {
        float4 a4 = make_float4(0.f, 0.f, 0.f, 0.f);
        int ar = m0 + lm;
        if (ar < M) a4 = *(const float4*)(A + (size_t)ar * K + k0 + lk);
        As[lk + 0][lm] = a4.x; As[lk + 1][lm] = a4.y;
        As[lk + 2][lm] = a4.z; As[lk + 3][lm] = a4.w;

        float4 b4 = make_float4(0.f, 0.f, 0.f, 0.f);
        int br = n0 + lm;
        if (br < Nn) b4 = *(const float4*)(B + (size_t)br * K + k0 + lk);
        Bs[lk + 0][lm] = b4.x; Bs[lk + 1][lm] = b4.y;
        Bs[lk + 2][lm] = b4.z; Bs[lk + 3][lm] = b4.w;
        __syncthreads();

#pragma unroll
        for (int kk = 0; kk < 16; kk++) {
            float4 av = *(const float4*)(&As[kk][ty * 4]);
            float4 bv = *(const float4*)(&Bs[kk][tx * 4]);
            float am[4] = {av.x, av.y, av.z, av.w};
            float bn[4] = {bv.x, bv.y, bv.z, bv.w};
#pragma unroll
            for (int i = 0; i < 4; i++)
#pragma unroll
                for (int j = 0; j < 4; j++) acc[i][j] = fmaf(am[i], bn[j], acc[i][j]);
        }
        __syncthreads();
    }

#pragma unroll
    for (int i = 0; i < 4; i++) {
        int row = m0 + ty * 4 + i;
        if (row >= M) continue;
#pragma unroll
        for (int j = 0; j < 4; j++) {
            int col = n0 + tx * 4 + j;
            if (col >= Nn) continue;
            float v = acc[i][j];
            if (EPI >= 1) v += bias[col];
            if (EPI == 2) v = 0.5f * v * (1.0f + erff(v * 0.70710678118654752f));
            if (EPI == 3) v += res[(size_t)row * Nn + col];
            C[(size_t)row * Nn + col] = v;
        }
    }
}

// ---------------- LayerNorm over DIM per token ----------------
__global__ void ln_kernel(const float* __restrict__ x, const float* __restrict__ g,
                          const float* __restrict__ b, float* __restrict__ y) {
    const int t = blockIdx.x;
    const int tid = threadIdx.x;                 // 256 threads
    const float* xr = x + (size_t)t * DIM;
    float v[3];
    float s = 0.f, s2 = 0.f;
    int cnt = 0;
    for (int c = tid; c < DIM; c += 256) { float val = xr[c]; v[cnt++] = val; s += val; s2 += val * val; }
    __shared__ float shs[8], shs2[8];
    for (int off = 16; off; off >>= 1) { s += __shfl_xor_sync(~0u, s, off); s2 += __shfl_xor_sync(~0u, s2, off); }
    int lane = tid & 31, w = tid >> 5;
    if (lane == 0) { shs[w] = s; shs2[w] = s2; }
    __syncthreads();
    float S = 0.f, S2 = 0.f;
    for (int i = 0; i < 8; i++) { S += shs[i]; S2 += shs2[i]; }
    const float mean = S / (float)DIM;
    const float var = S2 / (float)DIM - mean * mean;
    const float inv = rsqrtf(var + 1e-5f);
    cnt = 0;
    for (int c = tid; c < DIM; c += 256)
        y[(size_t)t * DIM + c] = (v[cnt++] - mean) * inv * g[c] + b[c];
}

// ---------------- Attention v4: block per (b,h), warp x 4 queries, K/V reuse ----------------
#define KPAD 76                        /* conflict-free pitch: 76 mod 32 = 12 */
#define NW3 16                         /* warps per block */
#define IQ 4                           /* queries per warp pass */
#define PPITCH 244                     /* prob row pitch (mult of 4) */

__global__ __launch_bounds__(512)
void attn4_kernel(const float* __restrict__ qkv, const float* __restrict__ btab,
                  float* __restrict__ o) {
    extern __shared__ float sh[];
    float* k_sh    = sh;                           // [SEQ*KPAD]
    float* v_sh    = k_sh + SEQ * KPAD;            // [SEQ*KPAD]
    float* p_sh    = v_sh + SEQ * KPAD;            // [NW3*IQ*PPITCH]
    float* q_sh    = p_sh + NW3 * IQ * PPITCH;     // [NW3*IQ*HDIM]
    float* bias_sh = q_sh + NW3 * IQ * HDIM;       // [2*SEQ-1]

    const int bh = blockIdx.x;
    const int h = bh % NH;
    const int b = bh / NH;
    const int tid = threadIdx.x;
    const int lane = tid & 31, w = tid >> 5;

    // block preload: k, v, bias
    for (int idx = tid; idx < SEQ * HDIM; idx += 512) {
        int j = idx / HDIM, c = idx % HDIM;
        size_t base = ((size_t)(b * SEQ + j) * 3) * DIM + h * HDIM + c;
        k_sh[j * KPAD + c] = qkv[base + DIM];
        v_sh[j * KPAD + c] = qkv[base + 2 * DIM];
    }
    for (int idx = tid; idx < 2 * SEQ - 1; idx += 512)
        bias_sh[idx] = btab[h * (2 * SEQ - 1) + idx];
    __syncthreads();            // the only block barrier

    const float scale = rsqrtf((float)HDIM);
    float* q_w  = q_sh + w * IQ * HDIM;
    float* p_w0 = p_sh + w * IQ * PPITCH;

    int jj[8], koff[8];
#pragma unroll
    for (int t = 0; t < 8; t++) {
        int j = lane + 32 * t;
        jj[t] = j;
        koff[t] = (j < SEQ ? j : SEQ - 1) * KPAD;
    }

    const int c2 = 2 * lane;
    const bool xtra = (lane < 2);
    const int cx = 64 + 2 * lane;

    for (int g = w; g * IQ < SEQ; g += NW3) {
        const int i0 = g * IQ;

        // warp-private q tile load (each query read once per block total)
        for (int idx = lane; idx < IQ * HDIM; idx += 32) {
            int qi = idx / HDIM, c = idx - qi * HDIM;
            int i = i0 + qi;
            q_w[idx] = (i < SEQ) ? qkv[((size_t)(b * SEQ + i) * 3) * DIM + h * HDIM + c] : 0.f;
        }
        __syncwarp();

        // ---- scores: k4 loads shared across IQ queries ----
        float sc[IQ][8];
#pragma unroll
        for (int qi = 0; qi < IQ; qi++)
#pragma unroll
            for (int t = 0; t < 8; t++) sc[qi][t] = 0.f;

#pragma unroll
        for (int c4 = 0; c4 < HDIM / 4; c4++) {
            float4 q4[IQ];
#pragma unroll
            for (int qi = 0; qi < IQ; qi++)
                q4[qi] = ((const float4*)(q_w + qi * HDIM))[c4];
#pragma unroll
            for (int t = 0; t < 8; t++) {
                float4 k4 = *(const float4*)(k_sh + koff[t] + 4 * c4);
#pragma unroll
                for (int qi = 0; qi < IQ; qi++) {
                    sc[qi][t] = fmaf(q4[qi].x, k4.x, sc[qi][t]);
                    sc[qi][t] = fmaf(q4[qi].y, k4.y, sc[qi][t]);
                    sc[qi][t] = fmaf(q4[qi].z, k4.z, sc[qi][t]);
                    sc[qi][t] = fmaf(q4[qi].w, k4.w, sc[qi][t]);
                }
            }
        }

        // ---- per-query softmax (warp shuffles) + prob writes ----
#pragma unroll
        for (int qi = 0; qi < IQ; qi++) {
            const int i = i0 + qi;
            const bool qv = (i < SEQ);
            float* p_w = p_w0 + qi * PPITCH;
            float mx = -1e30f;
#pragma unroll
            for (int t = 0; t < 8; t++) {
                if (qv && jj[t] < SEQ) {
                    sc[qi][t] = sc[qi][t] * scale + bias_sh[i - jj[t] + SEQ - 1];
                    mx = fmaxf(mx, sc[qi][t]);
                } else sc[qi][t] = -1e30f;
            }
#pragma unroll
            for (int off = 16; off; off >>= 1) mx = fmaxf(mx, __shfl_xor_sync(~0u, mx, off));
            float sum = 0.f;
#pragma unroll
            for (int t = 0; t < 8; t++) {
                float e = (qv && jj[t] < SEQ) ? __expf(sc[qi][t] - mx) : 0.f;
                sc[qi][t] = e;
                sum += e;
            }
#pragma unroll
            for (int off = 16; off; off >>= 1) sum += __shfl_xor_sync(~0u, sum, off);
            const float invS = qv ? (1.f / sum) : 0.f;
#pragma unroll
            for (int t = 0; t < 8; t++)
                if (jj[t] < PPITCH) p_w[jj[t]] = sc[qi][t] * invS;   // j=243 gets 0
        }
        __syncwarp();

        // ---- PV: v2 loads shared across IQ queries, probs as float4 broadcast ----
        float acc[IQ][2], accx[IQ][2];
#pragma unroll
        for (int qi = 0; qi < IQ; qi++) {
            acc[qi][0] = acc[qi][1] = 0.f;
            accx[qi][0] = accx[qi][1] = 0.f;
        }

#define PV_STEP(COMP, JOFF)                                                    \
        {                                                                      \
            const float* vrow = v_sh + (j4 + (JOFF)) * KPAD;                   \
            float2 v2 = *(const float2*)(vrow + c2);                           \
            _Pragma("unroll")                                                  \
            for (int qi = 0; qi < IQ; qi++) {                                  \
                acc[qi][0] = fmaf(P[qi].COMP, v2.x, acc[qi][0]);               \
                acc[qi][1] = fmaf(P[qi].COMP, v2.y, acc[qi][1]);               \
            }                                                                  \
            if (xtra) {                                                        \
                float2 vx = *(const float2*)(vrow + cx);                       \
                _Pragma("unroll")                                              \
                for (int qi = 0; qi < IQ; qi++) {                              \
                    accx[qi][0] = fmaf(P[qi].COMP, vx.x, accx[qi][0]);         \
                    accx[qi][1] = fmaf(P[qi].COMP, vx.y, accx[qi][1]);         \
                }                                                              \
            }                                                                  \
        }

#pragma unroll 1
        for (int j4 = 0; j4 < 240; j4 += 4) {
            float4 P[IQ];
#pragma unroll
            for (int qi = 0; qi < IQ; qi++)
                P[qi] = *(const float4*)(p_w0 + qi * PPITCH + j4);
            PV_STEP(x, 0)
            PV_STEP(y, 1)
            PV_STEP(z, 2)
            PV_STEP(w, 3)
        }
        // tail j = 240..242
        for (int j = 240; j < SEQ; j++) {
            const float* vrow = v_sh + j * KPAD;
            float2 v2 = *(const float2*)(vrow + c2);
#pragma unroll
            for (int qi = 0; qi < IQ; qi++) {
                float p = p_w0[qi * PPITCH + j];
                acc[qi][0] = fmaf(p, v2.x, acc[qi][0]);
                acc[qi][1] = fmaf(p, v2.y, acc[qi][1]);
            }
            if (xtra) {
                float2 vx = *(const float2*)(vrow + cx);
#pragma unroll
                for (int qi = 0; qi < IQ; qi++) {
                    float p = p_w0[qi * PPITCH + j];
                    accx[qi][0] = fmaf(p, vx.x, accx[qi][0]);
                    accx[qi][1] = fmaf(p, vx.y, accx[qi][1]);
                }
            }
        }
#undef PV_STEP

        // ---- write outputs ----
#pragma unroll
        for (int qi = 0; qi < IQ; qi++) {
            int i = i0 + qi;
            if (i >= SEQ) break;
            float* orow = o + (size_t)(b * SEQ + i) * DIM + h * HDIM;
            orow[c2] = acc[qi][0];
            orow[c2 + 1] = acc[qi][1];
            if (xtra) { orow[cx] = accx[qi][0]; orow[cx + 1] = accx[qi][1]; }
        }
        __syncwarp();
    }
}

#define ATTN4_SMEM ((2*SEQ*KPAD + NW3*IQ*PPITCH + NW3*IQ*HDIM + (2*SEQ-1)) * (int)sizeof(float))

// ---------------- expert logits: warp per (b,h,f) ----------------
__global__ void expert_logits_kernel(const float* __restrict__ xu, const float* __restrict__ s0,
                                     float* __restrict__ a) {
    const int gw = (blockIdx.x * blockDim.x + threadIdx.x) >> 5;
    if (gw >= BHN) return;
    const int lane = threadIdx.x & 31;
    const int f = gw % SEQ;
    const int h = (gw / SEQ) % NH;
    const int b = gw / (SEQ * NH);
    const float* xr = xu + (size_t)(b * SEQ + f) * UPD + h * UC;
    float xv[5];
#pragma unroll
    for (int q = 0; q < 5; q++) { int c = lane + 32 * q; xv[q] = (c < UC) ? xr[c] : 0.f; }
    const float* s0h = s0 + h * UC;
    float* ar = a + (size_t)gw * NSEED;
    for (int n = 0; n < NSEED; n++) {
        const float* sr = s0h + (size_t)n * UPD;
        float p = 0.f;
#pragma unroll
        for (int q = 0; q < 5; q++) { int c = lane + 32 * q; if (c < UC) p += xv[q] * sr[c]; }
        for (int off = 16; off; off >>= 1) p += __shfl_xor_sync(~0u, p, off);
        if (lane == 0) ar[n] = p;
    }
}

// ---------------- softmax over f (axis=-2): block per (b,h,n) ----------------
__global__ void softmax_f_kernel(float* __restrict__ a) {
    const int idx = blockIdx.x;            // b*H*NS + h*NS + n
    const int n = idx % NSEED;
    const int bh = idx / NSEED;
    float* base = a + (size_t)bh * SEQ * NSEED + n;
    const int tid = threadIdx.x;           // 256
    __shared__ float redm[8], redsum[8], bcast[2];
    const int lane = tid & 31, w = tid >> 5;
    float v = (tid < SEQ) ? base[(size_t)tid * NSEED] : -1e30f;
    float m = v;
    for (int off = 16; off; off >>= 1) m = fmaxf(m, __shfl_xor_sync(~0u, m, off));
    if (lane == 0) redm[w] = m;
    __syncthreads();
    if (tid == 0) {
        float mm = redm[0];
        for (int k = 1; k < 8; k++) mm = fmaxf(mm, redm[k]);
        bcast[0] = mm;
    }
    __syncthreads();
    const float M = bcast[0];
    float e = (tid < SEQ) ? __expf(v - M) : 0.f;
    float s = e;
    for (int off = 16; off; off >>= 1) s += __shfl_xor_sync(~0u, s, off);
    if (lane == 0) redsum[w] = s;
    __syncthreads();
    if (tid == 0) {
        float ss = 0.f;
        for (int k = 0; k < 8; k++) ss += redsum[k];
        bcast[1] = 1.f / ss;
    }
    __syncthreads();
    if (tid < SEQ) base[(size_t)tid * NSEED] = e * bcast[1];
}

// ---------------- normalize over n, accumulate mean, produce o2 ----------------
__global__ void expert_out_kernel(const float* __restrict__ a, const float* __restrict__ s1,
                                  float* __restrict__ o2, float* __restrict__ mean_acc) {
    const int gw = blockIdx.x;             // (b,h,f)
    const int f = gw % SEQ;
    const int h = (gw / SEQ) % NH;
    const int b = gw / (SEQ * NH);
    __shared__ float a_sh[NSEED];
    __shared__ float inv_s;
    const int tid = threadIdx.x;           // 160
    if (tid < NSEED) a_sh[tid] = a[(size_t)gw * NSEED + tid];
    __syncthreads();
    if (tid == 0) {
        float s = 0.f;
        for (int n = 0; n < NSEED; n++) s += a_sh[n];
        inv_s = 1.f / (1e-7f + s);
    }
    __syncthreads();
    if (tid < NSEED) {
        float val = a_sh[tid] * inv_s;
        a_sh[tid] = val;
        atomicAdd(mean_acc + tid, val);
    }
    __syncthreads();
    if (tid < UC) {
        const float* s1h = s1 + h * UC + tid;
        float acc = 0.f;
#pragma unroll
        for (int n = 0; n < NSEED; n++) acc += a_sh[n] * s1h[(size_t)n * UPD];
        o2[(size_t)(b * SEQ + f) * UPD + h * UC + tid] = acc;
    }
}

__global__ void zero_mean_kernel(float* __restrict__ mean_acc) {
    if (threadIdx.x < NSEED) mean_acc[threadIdx.x] = 0.f;
}

__global__ void finalize_mean_kernel(const float* __restrict__ mean_acc, float* __restrict__ out) {
    if (threadIdx.x < NSEED)
        out[threadIdx.x] = mean_acc[threadIdx.x] * (1.0f / (float)BHN);
}

// ---------------- driver ----------------
static inline dim3 gemm_grid64(int M, int Nn) { return dim3((Nn + 63) / 64, (M + 63) / 64); }
static inline dim3 gemm_grid128(int M, int Nn) { return dim3((Nn + 127) / 128, (M + 127) / 128); }

extern "C" void kernel_launch(void* const* d_in, const int* in_sizes, int n_in,
                              void* d_out, int out_size) {
    const float* x      = (const float*)d_in[0];
    const float* seed   = (const float*)d_in[1];
    const float* ln1_g  = (const float*)d_in[2];
    const float* ln1_b  = (const float*)d_in[3];
    const float* w_qkv  = (const float*)d_in[4];
    const float* w_proj = (const float*)d_in[5];
    const float* b_proj = (const float*)d_in[6];
    const float* b_tab  = (const float*)d_in[7];
    const float* ln2_g  = (const float*)d_in[8];
    const float* ln2_b  = (const float*)d_in[9];
    const float* mlp_w1 = (const float*)d_in[10];
    const float* mlp_b1 = (const float*)d_in[11];
    const float* mlp_w2 = (const float*)d_in[12];
    const float* mlp_b2 = (const float*)d_in[13];
    const float* eln1_g = (const float*)d_in[14];
    const float* eln1_b = (const float*)d_in[15];
    const float* w_trans= (const float*)d_in[16];
    const float* b_trans= (const float*)d_in[17];
    const float* w0     = (const float*)d_in[18];
    const float* b0     = (const float*)d_in[19];
    const float* w1     = (const float*)d_in[20];
    const float* b1     = (const float*)d_in[21];
    const float* w_proj2= (const float*)d_in[22];
    const float* b_proj2= (const float*)d_in[23];
    const float* eln2_g = (const float*)d_in[24];
    const float* eln2_b = (const float*)d_in[25];
    const float* emlp_w1= (const float*)d_in[26];
    const float* emlp_b1= (const float*)d_in[27];
    const float* emlp_w2= (const float*)d_in[28];
    const float* emlp_b2= (const float*)d_in[29];

    float* xbuf = (float*)d_out;                  // running x lives in d_out
    float* out_mean = (float*)d_out + (size_t)TOK * DIM;

    float *p_h, *p_qkv, *p_o, *p_big, *p_a, *p_s0, *p_s1, *p_mean;
    cudaGetSymbolAddress((void**)&p_h,   g_h);
    cudaGetSymbolAddress((void**)&p_qkv, g_qkv);
    cudaGetSymbolAddress((void**)&p_o,   g_o);
    cudaGetSymbolAddress((void**)&p_big, g_big);
    cudaGetSymbolAddress((void**)&p_a,   g_a);
    cudaGetSymbolAddress((void**)&p_s0,  g_s0);
    cudaGetSymbolAddress((void**)&p_s1,  g_s1);
    cudaGetSymbolAddress((void**)&p_mean,g_mean);

    cudaFuncSetAttribute(attn4_kernel, cudaFuncAttributeMaxDynamicSharedMemorySize, ATTN4_SMEM);

    // x -> output buffer (running residual stream)
    cudaMemcpyAsync(xbuf, x, (size_t)TOK * DIM * sizeof(float), cudaMemcpyDeviceToDevice);
    zero_mean_kernel<<<1, 32>>>(p_mean);

    // ---- block 1: attention ----
    ln_kernel<<<TOK, 256>>>(xbuf, ln1_g, ln1_b, p_h);
    gemm_tf32_kernel<0><<<gemm_grid128(TOK, 3 * DIM), 256>>>(p_h, w_qkv, nullptr, nullptr, p_qkv, TOK, 3 * DIM, DIM);
    attn4_kernel<<<BSZn * NH, 512, ATTN4_SMEM>>>(p_qkv, b_tab, p_o);
    gemm_tf32_kernel<3><<<gemm_grid128(TOK, DIM), 256>>>(p_o, w_proj, b_proj, xbuf, xbuf, TOK, DIM, DIM);

    // ---- block 2: MLP ----
    ln_kernel<<<TOK, 256>>>(xbuf, ln2_g, ln2_b, p_h);
    gemm_tf32_kernel<2><<<gemm_grid128(TOK, MLP1), 256>>>(p_h, mlp_w1, mlp_b1, nullptr, p_big, TOK, MLP1, DIM);
    gemm_tf32_kernel<3><<<gemm_grid128(TOK, DIM), 256>>>(p_big, mlp_w2, mlp_b2, xbuf, xbuf, TOK, DIM, MLP1);

    // ---- block 3: seed-expert attention ----
    ln_kernel<<<TOK, 256>>>(xbuf, eln1_g, eln1_b, p_h);
    gemm_tf32_kernel<1><<<gemm_grid128(TOK, UPD), 256>>>(p_h, w_trans, b_trans, nullptr, p_qkv, TOK, UPD, DIM);
    gemm_kernel<1><<<gemm_grid64(NSEED, UPD), 256>>>(seed, w0, b0, nullptr, p_s0, NSEED, UPD, DIM);
    gemm_kernel<1><<<gemm_grid64(NSEED, UPD), 256>>>(seed, w1, b1, nullptr, p_s1, NSEED, UPD, DIM);
    expert_logits_kernel<<<(BHN * 32 + 127) / 128, 128>>>(p_qkv, p_s0, p_a);
    softmax_f_kernel<<<BSZn * NH * NSEED, 256>>>(p_a);
    expert_out_kernel<<<BHN, 160>>>(p_a, p_s1, p_big, p_mean);
    finalize_mean_kernel<<<1, 32>>>(p_mean, out_mean);
    gemm_tf32_kernel<3><<<gemm_grid128(TOK, DIM), 256>>>(p_big, w_proj2, b_proj2, xbuf, xbuf, TOK, DIM, UPD);

    // ---- block 4: expert MLP ----
    ln_kernel<<<TOK, 256>>>(xbuf, eln2_g, eln2_b, p_h);
    gemm_tf32_kernel<2><<<gemm_grid128(TOK, MLP2), 256>>>(p_h, emlp_w1, emlp_b1, nullptr, p_big, TOK, MLP2, DIM);
    gemm_tf32_kernel<3><<<gemm_grid128(TOK, DIM), 256>>>(p_big, emlp_w2, emlp_b2, xbuf, xbuf, TOK, DIM, MLP2);
}

// round 14
// speedup vs baseline: 1.3865x; 1.0976x over previous
#include <cuda_runtime.h>
#include <math.h>

#define BSZn 32
#define SEQ 243
#define DIM 544
#define NH 8
#define HDIM 68
#define NSEED 17
#define UPD 1088
#define UC 136
#define MLP1 2176
#define MLP2 1088
#define TOK (BSZn*SEQ)          /* 7776 */
#define BHN (BSZn*NH*SEQ)       /* 62208 */

// ---------------- scratch (static device globals; no allocation) ----------------
__device__ float g_qkv[TOK*3*DIM];      // qkv, later xu
__device__ float g_o[TOK*DIM];          // attention output
__device__ float g_big[TOK*MLP1];       // mlp hidden / o2 / emlp hidden
__device__ float g_a[BHN*NSEED];        // expert attention weights
__device__ float g_s0[NSEED*UPD];
__device__ float g_s1[NSEED*UPD];
__device__ float g_mean[NSEED];
__device__ float g_stats[TOK*2];        // per-token LN (mean, inv)

// ---------------- LN stats: warp per token ----------------
__global__ void ln_stats_kernel(const float* __restrict__ x, float* __restrict__ stats) {
    const int warp = (blockIdx.x * blockDim.x + threadIdx.x) >> 5;
    if (warp >= TOK) return;
    const int lane = threadIdx.x & 31;
    const float* xr = x + (size_t)warp * DIM;
    float s = 0.f, s2 = 0.f;
#pragma unroll
    for (int i = 0; i < 17; i++) {          // 544 = 32*17 exact
        float v = xr[lane + 32 * i];
        s += v; s2 += v * v;
    }
#pragma unroll
    for (int off = 16; off; off >>= 1) {
        s  += __shfl_xor_sync(~0u, s,  off);
        s2 += __shfl_xor_sync(~0u, s2, off);
    }
    if (lane == 0) {
        float mean = s * (1.f / (float)DIM);
        float var  = s2 * (1.f / (float)DIM) - mean * mean;
        stats[2 * warp]     = mean;
        stats[2 * warp + 1] = rsqrtf(var + 1e-5f);
    }
}

// ======================= tf32 tensor-core GEMM =======================
// C[M,N] = op(A)[M,K] * B[N,K]^T (+epilogue). K % 32 == 0.
// LNA=1: A element -> (a - mean_row)*inv_row*g[col] + b[col]  (fused LayerNorm)
// EPI: 0 none, 1 +bias, 2 +bias+GELU(exact), 3 +bias+residual

__device__ __forceinline__ unsigned cvt_tf32(float x) {
    unsigned u;
    asm("cvt.rna.tf32.f32 %0, %1;" : "=r"(u) : "f"(x));
    return u;
}

__device__ __forceinline__ void mma_tf32(float* d, const unsigned* a, unsigned b0, unsigned b1) {
    asm volatile("mma.sync.aligned.m16n8k8.row.col.f32.tf32.tf32.f32 "
                 "{%0,%1,%2,%3}, {%4,%5,%6,%7}, {%8,%9}, {%0,%1,%2,%3};\n"
                 : "+f"(d[0]), "+f"(d[1]), "+f"(d[2]), "+f"(d[3])
                 : "r"(a[0]), "r"(a[1]), "r"(a[2]), "r"(a[3]), "r"(b0), "r"(b1));
}

template<int EPI, int LNA>
__global__ __launch_bounds__(256, 2)
void gemm_tf32_kernel(const float* __restrict__ A, const float* __restrict__ B,
                      const float* __restrict__ bias, const float* __restrict__ res,
                      float* __restrict__ C, int M, int Nn, int K,
                      const float* __restrict__ lnstats,
                      const float* __restrict__ lng, const float* __restrict__ lnb) {
    __shared__ unsigned As[128 * 36];   // [row][k], pad 36 -> conflict-free frag loads
    __shared__ unsigned Bs[128 * 36];   // [col(n)][k]
    const int tid  = threadIdx.x;
    const int warp = tid >> 5, lane = tid & 31;
    const int wm = (warp >> 1) * 32;    // warp row base (4 warps along M)
    const int wn = (warp & 1) * 64;     // warp col base (2 warps along N)
    const int q  = lane & 3;            // k quad
    const int rg = lane >> 2;           // row/col group 0..7
    const int m0 = blockIdx.y * 128, n0 = blockIdx.x * 128;

    // staging map: each thread loads 4 float4 per matrix
    const int lr = tid >> 3;            // base row 0..31 (stride 32)
    const int lc = (tid & 7) * 4;       // k offset 0..28

    float4 ra[4], rb[4];
    float acc[2][8][4];
#pragma unroll
    for (int i = 0; i < 2; i++)
#pragma unroll
        for (int j = 0; j < 8; j++)
#pragma unroll
            for (int c = 0; c < 4; c++) acc[i][j][c] = 0.f;

    const int T = K >> 5;

    // load tile t into registers (optionally applying fused LayerNorm to A)
    auto load_t = [&](int t) {
        const int kb = t * 32 + lc;
        float4 g4, bb4;
        if (LNA) {
            g4  = *(const float4*)(lng + kb);
            bb4 = *(const float4*)(lnb + kb);
        }
#pragma unroll
        for (int p = 0; p < 4; p++) {
            int r = lr + p * 32;
            int ar = m0 + r;
            if (ar < M) {
                float4 v = *(const float4*)(A + (size_t)ar * K + kb);
                if (LNA) {
                    float2 st = *(const float2*)(lnstats + 2 * ar);
                    v.x = (v.x - st.x) * st.y * g4.x + bb4.x;
                    v.y = (v.y - st.x) * st.y * g4.y + bb4.y;
                    v.z = (v.z - st.x) * st.y * g4.z + bb4.z;
                    v.w = (v.w - st.x) * st.y * g4.w + bb4.w;
                }
                ra[p] = v;
            } else ra[p] = make_float4(0.f, 0.f, 0.f, 0.f);
            int br = n0 + r;
            rb[p] = (br < Nn) ? *(const float4*)(B + (size_t)br * K + kb)
                              : make_float4(0.f, 0.f, 0.f, 0.f);
        }
    };
    // convert + store registers into smem
    auto store_t = [&]() {
#pragma unroll
        for (int p = 0; p < 4; p++) {
            int r = lr + p * 32;
            unsigned* da = &As[r * 36 + lc];
            da[0] = cvt_tf32(ra[p].x); da[1] = cvt_tf32(ra[p].y);
            da[2] = cvt_tf32(ra[p].z); da[3] = cvt_tf32(ra[p].w);
            unsigned* db = &Bs[r * 36 + lc];
            db[0] = cvt_tf32(rb[p].x); db[1] = cvt_tf32(rb[p].y);
            db[2] = cvt_tf32(rb[p].z); db[3] = cvt_tf32(rb[p].w);
        }
    };

    load_t(0);
    store_t();
    __syncthreads();

    for (int t = 0; t < T; t++) {
        if (t + 1 < T) load_t(t + 1);   // global prefetch overlaps compute

#pragma unroll
        for (int s = 0; s < 4; s++) {
            const int k0 = s * 8;
            unsigned afr[2][4];
#pragma unroll
            for (int mt = 0; mt < 2; mt++) {
                int r = wm + mt * 16 + rg;
                afr[mt][0] = As[r * 36 + k0 + q];
                afr[mt][1] = As[(r + 8) * 36 + k0 + q];
                afr[mt][2] = As[r * 36 + k0 + q + 4];
                afr[mt][3] = As[(r + 8) * 36 + k0 + q + 4];
            }
#pragma unroll
            for (int nt = 0; nt < 8; nt++) {
                int cb = wn + nt * 8 + rg;
                unsigned b0 = Bs[cb * 36 + k0 + q];
                unsigned b1 = Bs[cb * 36 + k0 + q + 4];
                mma_tf32(acc[0][nt], afr[0], b0, b1);
                mma_tf32(acc[1][nt], afr[1], b0, b1);
            }
        }

        if (t + 1 < T) {
            __syncthreads();   // all warps done reading smem
            store_t();
            __syncthreads();   // stores visible
        }
    }

    // epilogue
#pragma unroll
    for (int mt = 0; mt < 2; mt++)
#pragma unroll
        for (int half = 0; half < 2; half++) {
            int row = m0 + wm + mt * 16 + rg + half * 8;
            if (row >= M) continue;
#pragma unroll
            for (int nt = 0; nt < 8; nt++) {
                int col = n0 + wn + nt * 8 + 2 * q;
                if (col >= Nn) continue;
                float v0 = acc[mt][nt][half * 2 + 0];
                float v1 = acc[mt][nt][half * 2 + 1];
                if (EPI >= 1) { v0 += bias[col]; v1 += bias[col + 1]; }
                if (EPI == 2) {
                    v0 = 0.5f * v0 * (1.0f + erff(v0 * 0.70710678118654752f));
                    v1 = 0.5f * v1 * (1.0f + erff(v1 * 0.70710678118654752f));
                }
                size_t idx = (size_t)row * Nn + col;
                if (EPI == 3) { v0 += res[idx]; v1 += res[idx + 1]; }
                C[idx] = v0; C[idx + 1] = v1;
            }
        }
}

// ---------------- batched seed GEMM (s0 & s1 in one launch, FFMA path) ----------------
// C_z[17, UPD] = seed[17, DIM] * Wz[UPD, DIM]^T + bz ; z = blockIdx.z
__global__ void seed_gemm_kernel(const float* __restrict__ seed,
                                 const float* __restrict__ w0, const float* __restrict__ b0,
                                 const float* __restrict__ w1, const float* __restrict__ b1,
                                 float* __restrict__ s0out, float* __restrict__ s1out) {
    const float* B    = blockIdx.z ? w1 : w0;
    const float* bias = blockIdx.z ? b1 : b0;
    float*       C    = blockIdx.z ? s1out : s0out;
    const int M = NSEED, Nn = UPD, K = DIM;

    __shared__ float As[16][64];
    __shared__ float Bs[16][64];
    const int tid = threadIdx.x;
    const int n0 = blockIdx.x * 64;
    const int ty = tid >> 4;
    const int tx = tid & 15;
    const int lm = tid >> 2;
    const int lk = (tid & 3) * 4;

    float acc[4][4];
#pragma unroll
    for (int i = 0; i < 4; i++)
#pragma unroll
        for (int j = 0; j < 4; j++) acc[i][j] = 0.f;

    for (int k0 = 0; k0 < K; k0 += 16) {
        float4 a4 = make_float4(0.f, 0.f, 0.f, 0.f);
        if (lm < M) a4 = *(const float4*)(seed + (size_t)lm * K + k0 + lk);
        As[lk + 0][lm] = a4.x; As[lk + 1][lm] = a4.y;
        As[lk + 2][lm] = a4.z; As[lk + 3][lm] = a4.w;

        float4 b4 = make_float4(0.f, 0.f, 0.f, 0.f);
        int br = n0 + lm;
        if (br < Nn) b4 = *(const float4*)(B + (size_t)br * K + k0 + lk);
        Bs[lk + 0][lm] = b4.x; Bs[lk + 1][lm] = b4.y;
        Bs[lk + 2][lm] = b4.z; Bs[lk + 3][lm] = b4.w;
        __syncthreads();

#pragma unroll
        for (int kk = 0; kk < 16; kk++) {
            float4 av = *(const float4*)(&As[kk][ty * 4]);
            float4 bv = *(const float4*)(&Bs[kk][tx * 4]);
            float am[4] = {av.x, av.y, av.z, av.w};
            float bn[4] = {bv.x, bv.y, bv.z, bv.w};
#pragma unroll
            for (int i = 0; i < 4; i++)
#pragma unroll
                for (int j = 0; j < 4; j++) acc[i][j] = fmaf(am[i], bn[j], acc[i][j]);
        }
        __syncthreads();
    }

#pragma unroll
    for (int i = 0; i < 4; i++) {
        int row = ty * 4 + i;
        if (row >= M) continue;
#pragma unroll
        for (int j = 0; j < 4; j++) {
            int col = n0 + tx * 4 + j;
            if (col >= Nn) continue;
            C[(size_t)row * Nn + col] = acc[i][j] + bias[col];
        }
    }
}

// ---------------- Attention v4: block per (b,h), warp x 4 queries, K/V reuse ----------------
#define KPAD 76                        /* conflict-free pitch */
#define NW3 16                         /* warps per block */
#define IQ 4                           /* queries per warp pass */
#define PPITCH 244                     /* prob row pitch (mult of 4) */

__global__ __launch_bounds__(512)
void attn4_kernel(const float* __restrict__ qkv, const float* __restrict__ btab,
                  float* __restrict__ o) {
    extern __shared__ float sh[];
    float* k_sh    = sh;                           // [SEQ*KPAD]
    float* v_sh    = k_sh + SEQ * KPAD;            // [SEQ*KPAD]
    float* p_sh    = v_sh + SEQ * KPAD;            // [NW3*IQ*PPITCH]
    float* q_sh    = p_sh + NW3 * IQ * PPITCH;     // [NW3*IQ*HDIM]
    float* bias_sh = q_sh + NW3 * IQ * HDIM;       // [2*SEQ-1]

    const int bh = blockIdx.x;
    const int h = bh % NH;
    const int b = bh / NH;
    const int tid = threadIdx.x;
    const int lane = tid & 31, w = tid >> 5;

    // block preload: k, v, bias
    for (int idx = tid; idx < SEQ * HDIM; idx += 512) {
        int j = idx / HDIM, c = idx % HDIM;
        size_t base = ((size_t)(b * SEQ + j) * 3) * DIM + h * HDIM + c;
        k_sh[j * KPAD + c] = qkv[base + DIM];
        v_sh[j * KPAD + c] = qkv[base + 2 * DIM];
    }
    for (int idx = tid; idx < 2 * SEQ - 1; idx += 512)
        bias_sh[idx] = btab[h * (2 * SEQ - 1) + idx];
    __syncthreads();            // the only block barrier

    const float scale = rsqrtf((float)HDIM);
    float* q_w  = q_sh + w * IQ * HDIM;
    float* p_w0 = p_sh + w * IQ * PPITCH;

    int jj[8], koff[8];
#pragma unroll
    for (int t = 0; t < 8; t++) {
        int j = lane + 32 * t;
        jj[t] = j;
        koff[t] = (j < SEQ ? j : SEQ - 1) * KPAD;
    }

    const int c2 = 2 * lane;
    const bool xtra = (lane < 2);
    const int cx = 64 + 2 * lane;

    for (int g = w; g * IQ < SEQ; g += NW3) {
        const int i0 = g * IQ;

        // warp-private q tile load (each query read once per block total)
        for (int idx = lane; idx < IQ * HDIM; idx += 32) {
            int qi = idx / HDIM, c = idx - qi * HDIM;
            int i = i0 + qi;
            q_w[idx] = (i < SEQ) ? qkv[((size_t)(b * SEQ + i) * 3) * DIM + h * HDIM + c] : 0.f;
        }
        __syncwarp();

        // ---- scores: k4 loads shared across IQ queries ----
        float sc[IQ][8];
#pragma unroll
        for (int qi = 0; qi < IQ; qi++)
#pragma unroll
            for (int t = 0; t < 8; t++) sc[qi][t] = 0.f;

#pragma unroll
        for (int c4 = 0; c4 < HDIM / 4; c4++) {
            float4 q4[IQ];
#pragma unroll
            for (int qi = 0; qi < IQ; qi++)
                q4[qi] = ((const float4*)(q_w + qi * HDIM))[c4];
#pragma unroll
            for (int t = 0; t < 8; t++) {
                float4 k4 = *(const float4*)(k_sh + koff[t] + 4 * c4);
#pragma unroll
                for (int qi = 0; qi < IQ; qi++) {
                    sc[qi][t] = fmaf(q4[qi].x, k4.x, sc[qi][t]);
                    sc[qi][t] = fmaf(q4[qi].y, k4.y, sc[qi][t]);
                    sc[qi][t] = fmaf(q4[qi].z, k4.z, sc[qi][t]);
                    sc[qi][t] = fmaf(q4[qi].w, k4.w, sc[qi][t]);
                }
            }
        }

        // ---- per-query softmax (warp shuffles) + prob writes ----
#pragma unroll
        for (int qi = 0; qi < IQ; qi++) {
            const int i = i0 + qi;
            const bool qv = (i < SEQ);
            float* p_w = p_w0 + qi * PPITCH;
            float mx = -1e30f;
#pragma unroll
            for (int t = 0; t < 8; t++) {
                if (qv && jj[t] < SEQ) {
                    sc[qi][t] = sc[qi][t] * scale + bias_sh[i - jj[t] + SEQ - 1];
                    mx = fmaxf(mx, sc[qi][t]);
                } else sc[qi][t] = -1e30f;
            }
#pragma unroll
            for (int off = 16; off; off >>= 1) mx = fmaxf(mx, __shfl_xor_sync(~0u, mx, off));
            float sum = 0.f;
#pragma unroll
            for (int t = 0; t < 8; t++) {
                float e = (qv && jj[t] < SEQ) ? __expf(sc[qi][t] - mx) : 0.f;
                sc[qi][t] = e;
                sum += e;
            }
#pragma unroll
            for (int off = 16; off; off >>= 1) sum += __shfl_xor_sync(~0u, sum, off);
            const float invS = qv ? (1.f / sum) : 0.f;
#pragma unroll
            for (int t = 0; t < 8; t++)
                if (jj[t] < PPITCH) p_w[jj[t]] = sc[qi][t] * invS;   // j=243 gets 0
        }
        __syncwarp();

        // ---- PV: v2 loads shared across IQ queries, probs as float4 broadcast ----
        float acc[IQ][2], accx[IQ][2];
#pragma unroll
        for (int qi = 0; qi < IQ; qi++) {
            acc[qi][0] = acc[qi][1] = 0.f;
            accx[qi][0] = accx[qi][1] = 0.f;
        }

#define PV_STEP(COMP, JOFF)                                                    \
        {                                                                      \
            const float* vrow = v_sh + (j4 + (JOFF)) * KPAD;                   \
            float2 v2 = *(const float2*)(vrow + c2);                           \
            _Pragma("unroll")                                                  \
            for (int qi = 0; qi < IQ; qi++) {                                  \
                acc[qi][0] = fmaf(P[qi].COMP, v2.x, acc[qi][0]);               \
                acc[qi][1] = fmaf(P[qi].COMP, v2.y, acc[qi][1]);               \
            }                                                                  \
            if (xtra) {                                                        \
                float2 vx = *(const float2*)(vrow + cx);                       \
                _Pragma("unroll")                                              \
                for (int qi = 0; qi < IQ; qi++) {                              \
                    accx[qi][0] = fmaf(P[qi].COMP, vx.x, accx[qi][0]);         \
                    accx[qi][1] = fmaf(P[qi].COMP, vx.y, accx[qi][1]);         \
                }                                                              \
            }                                                                  \
        }

#pragma unroll 1
        for (int j4 = 0; j4 < 240; j4 += 4) {
            float4 P[IQ];
#pragma unroll
            for (int qi = 0; qi < IQ; qi++)
                P[qi] = *(const float4*)(p_w0 + qi * PPITCH + j4);
            PV_STEP(x, 0)
            PV_STEP(y, 1)
            PV_STEP(z, 2)
            PV_STEP(w, 3)
        }
        // tail j = 240..242
        for (int j = 240; j < SEQ; j++) {
            const float* vrow = v_sh + j * KPAD;
            float2 v2 = *(const float2*)(vrow + c2);
#pragma unroll
            for (int qi = 0; qi < IQ; qi++) {
                float p = p_w0[qi * PPITCH + j];
                acc[qi][0] = fmaf(p, v2.x, acc[qi][0]);
                acc[qi][1] = fmaf(p, v2.y, acc[qi][1]);
            }
            if (xtra) {
                float2 vx = *(const float2*)(vrow + cx);
#pragma unroll
                for (int qi = 0; qi < IQ; qi++) {
                    float p = p_w0[qi * PPITCH + j];
                    accx[qi][0] = fmaf(p, vx.x, accx[qi][0]);
                    accx[qi][1] = fmaf(p, vx.y, accx[qi][1]);
                }
            }
        }
#undef PV_STEP

        // ---- write outputs ----
#pragma unroll
        for (int qi = 0; qi < IQ; qi++) {
            int i = i0 + qi;
            if (i >= SEQ) break;
            float* orow = o + (size_t)(b * SEQ + i) * DIM + h * HDIM;
            orow[c2] = acc[qi][0];
            orow[c2 + 1] = acc[qi][1];
            if (xtra) { orow[cx] = accx[qi][0]; orow[cx + 1] = accx[qi][1]; }
        }
        __syncwarp();
    }
}

#define ATTN4_SMEM ((2*SEQ*KPAD + NW3*IQ*PPITCH + NW3*IQ*HDIM + (2*SEQ-1)) * (int)sizeof(float))

// ---------------- expert logits: warp per (b,h,f) ----------------
__global__ void expert_logits_kernel(const float* __restrict__ xu, const float* __restrict__ s0,
                                     float* __restrict__ a) {
    const int gw = (blockIdx.x * blockDim.x + threadIdx.x) >> 5;
    if (gw >= BHN) return;
    const int lane = threadIdx.x & 31;
    const int f = gw % SEQ;
    const int h = (gw / SEQ) % NH;
    const int b = gw / (SEQ * NH);
    const float* xr = xu + (size_t)(b * SEQ + f) * UPD + h * UC;
    float xv[5];
#pragma unroll
    for (int q = 0; q < 5; q++) { int c = lane + 32 * q; xv[q] = (c < UC) ? xr[c] : 0.f; }
    const float* s0h = s0 + h * UC;
    float* ar = a + (size_t)gw * NSEED;
    for (int n = 0; n < NSEED; n++) {
        const float* sr = s0h + (size_t)n * UPD;
        float p = 0.f;
#pragma unroll
        for (int q = 0; q < 5; q++) { int c = lane + 32 * q; if (c < UC) p += xv[q] * sr[c]; }
        for (int off = 16; off; off >>= 1) p += __shfl_xor_sync(~0u, p, off);
        if (lane == 0) ar[n] = p;
    }
}

// ---------------- softmax over f (axis=-2): block per (b,h,n) ----------------
__global__ void softmax_f_kernel(float* __restrict__ a) {
    const int idx = blockIdx.x;            // b*H*NS + h*NS + n
    const int n = idx % NSEED;
    const int bh = idx / NSEED;
    float* base = a + (size_t)bh * SEQ * NSEED + n;
    const int tid = threadIdx.x;           // 256
    __shared__ float redm[8], redsum[8], bcast[2];
    const int lane = tid & 31, w = tid >> 5;
    float v = (tid < SEQ) ? base[(size_t)tid * NSEED] : -1e30f;
    float m = v;
    for (int off = 16; off; off >>= 1) m = fmaxf(m, __shfl_xor_sync(~0u, m, off));
    if (lane == 0) redm[w] = m;
    __syncthreads();
    if (tid == 0) {
        float mm = redm[0];
        for (int k = 1; k < 8; k++) mm = fmaxf(mm, redm[k]);
        bcast[0] = mm;
    }
    __syncthreads();
    const float M = bcast[0];
    float e = (tid < SEQ) ? __expf(v - M) : 0.f;
    float s = e;
    for (int off = 16; off; off >>= 1) s += __shfl_xor_sync(~0u, s, off);
    if (lane == 0) redsum[w] = s;
    __syncthreads();
    if (tid == 0) {
        float ss = 0.f;
        for (int k = 0; k < 8; k++) ss += redsum[k];
        bcast[1] = 1.f / ss;
    }
    __syncthreads();
    if (tid < SEQ) base[(size_t)tid * NSEED] = e * bcast[1];
}

// ---------------- normalize over n, accumulate mean, produce o2 ----------------
__global__ void expert_out_kernel(const float* __restrict__ a, const float* __restrict__ s1,
                                  float* __restrict__ o2, float* __restrict__ mean_acc) {
    const int gw = blockIdx.x;             // (b,h,f)
    const int f = gw % SEQ;
    const int h = (gw / SEQ) % NH;
    const int b = gw / (SEQ * NH);
    __shared__ float a_sh[NSEED];
    __shared__ float inv_s;
    const int tid = threadIdx.x;           // 160
    if (tid < NSEED) a_sh[tid] = a[(size_t)gw * NSEED + tid];
    __syncthreads();
    if (tid == 0) {
        float s = 0.f;
        for (int n = 0; n < NSEED; n++) s += a_sh[n];
        inv_s = 1.f / (1e-7f + s);
    }
    __syncthreads();
    if (tid < NSEED) {
        float val = a_sh[tid] * inv_s;
        a_sh[tid] = val;
        atomicAdd(mean_acc + tid, val);
    }
    __syncthreads();
    if (tid < UC) {
        const float* s1h = s1 + h * UC + tid;
        float acc = 0.f;
#pragma unroll
        for (int n = 0; n < NSEED; n++) acc += a_sh[n] * s1h[(size_t)n * UPD];
        o2[(size_t)(b * SEQ + f) * UPD + h * UC + tid] = acc;
    }
}

__global__ void zero_mean_kernel(float* __restrict__ mean_acc) {
    if (threadIdx.x < NSEED) mean_acc[threadIdx.x] = 0.f;
}

__global__ void finalize_mean_kernel(const float* __restrict__ mean_acc, float* __restrict__ out) {
    if (threadIdx.x < NSEED)
        out[threadIdx.x] = mean_acc[threadIdx.x] * (1.0f / (float)BHN);
}

// ---------------- driver ----------------
static inline dim3 gemm_grid128(int M, int Nn) { return dim3((Nn + 127) / 128, (M + 127) / 128); }

extern "C" void kernel_launch(void* const* d_in, const int* in_sizes, int n_in,
                              void* d_out, int out_size) {
    const float* x      = (const float*)d_in[0];
    const float* seed   = (const float*)d_in[1];
    const float* ln1_g  = (const float*)d_in[2];
    const float* ln1_b  = (const float*)d_in[3];
    const float* w_qkv  = (const float*)d_in[4];
    const float* w_proj = (const float*)d_in[5];
    const float* b_proj = (const float*)d_in[6];
    const float* b_tab  = (const float*)d_in[7];
    const float* ln2_g  = (const float*)d_in[8];
    const float* ln2_b  = (const float*)d_in[9];
    const float* mlp_w1 = (const float*)d_in[10];
    const float* mlp_b1 = (const float*)d_in[11];
    const float* mlp_w2 = (const float*)d_in[12];
    const float* mlp_b2 = (const float*)d_in[13];
    const float* eln1_g = (const float*)d_in[14];
    const float* eln1_b = (const float*)d_in[15];
    const float* w_trans= (const float*)d_in[16];
    const float* b_trans= (const float*)d_in[17];
    const float* w0     = (const float*)d_in[18];
    const float* b0     = (const float*)d_in[19];
    const float* w1     = (const float*)d_in[20];
    const float* b1     = (const float*)d_in[21];
    const float* w_proj2= (const float*)d_in[22];
    const float* b_proj2= (const float*)d_in[23];
    const float* eln2_g = (const float*)d_in[24];
    const float* eln2_b = (const float*)d_in[25];
    const float* emlp_w1= (const float*)d_in[26];
    const float* emlp_b1= (const float*)d_in[27];
    const float* emlp_w2= (const float*)d_in[28];
    const float* emlp_b2= (const float*)d_in[29];

    float* xbuf = (float*)d_out;                  // running x lives in d_out
    float* out_mean = (float*)d_out + (size_t)TOK * DIM;

    float *p_qkv, *p_o, *p_big, *p_a, *p_s0, *p_s1, *p_mean, *p_st;
    cudaGetSymbolAddress((void**)&p_qkv, g_qkv);
    cudaGetSymbolAddress((void**)&p_o,   g_o);
    cudaGetSymbolAddress((void**)&p_big, g_big);
    cudaGetSymbolAddress((void**)&p_a,   g_a);
    cudaGetSymbolAddress((void**)&p_s0,  g_s0);
    cudaGetSymbolAddress((void**)&p_s1,  g_s1);
    cudaGetSymbolAddress((void**)&p_mean,g_mean);
    cudaGetSymbolAddress((void**)&p_st,  g_stats);

    cudaFuncSetAttribute(attn4_kernel, cudaFuncAttributeMaxDynamicSharedMemorySize, ATTN4_SMEM);

    zero_mean_kernel<<<1, 32>>>(p_mean);

    // ---- block 1: attention (LN fused into qkv GEMM; residual reads original x) ----
    ln_stats_kernel<<<(TOK * 32 + 255) / 256, 256>>>(x, p_st);
    gemm_tf32_kernel<0, 1><<<gemm_grid128(TOK, 3 * DIM), 256>>>(
        x, w_qkv, nullptr, nullptr, p_qkv, TOK, 3 * DIM, DIM, p_st, ln1_g, ln1_b);
    attn4_kernel<<<BSZn * NH, 512, ATTN4_SMEM>>>(p_qkv, b_tab, p_o);
    gemm_tf32_kernel<3, 0><<<gemm_grid128(TOK, DIM), 256>>>(
        p_o, w_proj, b_proj, x, xbuf, TOK, DIM, DIM, nullptr, nullptr, nullptr);

    // ---- block 2: MLP ----
    ln_stats_kernel<<<(TOK * 32 + 255) / 256, 256>>>(xbuf, p_st);
    gemm_tf32_kernel<2, 1><<<gemm_grid128(TOK, MLP1), 256>>>(
        xbuf, mlp_w1, mlp_b1, nullptr, p_big, TOK, MLP1, DIM, p_st, ln2_g, ln2_b);
    gemm_tf32_kernel<3, 0><<<gemm_grid128(TOK, DIM), 256>>>(
        p_big, mlp_w2, mlp_b2, xbuf, xbuf, TOK, DIM, MLP1, nullptr, nullptr, nullptr);

    // ---- block 3: seed-expert attention ----
    ln_stats_kernel<<<(TOK * 32 + 255) / 256, 256>>>(xbuf, p_st);
    gemm_tf32_kernel<1, 1><<<gemm_grid128(TOK, UPD), 256>>>(
        xbuf, w_trans, b_trans, nullptr, p_qkv, TOK, UPD, DIM, p_st, eln1_g, eln1_b);
    seed_gemm_kernel<<<dim3(UPD / 64, 1, 2), 256>>>(seed, w0, b0, w1, b1, p_s0, p_s1);
    expert_logits_kernel<<<(BHN * 32 + 127) / 128, 128>>>(p_qkv, p_s0, p_a);
    softmax_f_kernel<<<BSZn * NH * NSEED, 256>>>(p_a);
    expert_out_kernel<<<BHN, 160>>>(p_a, p_s1, p_big, p_mean);
    finalize_mean_kernel<<<1, 32>>>(p_mean, out_mean);
    gemm_tf32_kernel<3, 0><<<gemm_grid128(TOK, DIM), 256>>>(
        p_big, w_proj2, b_proj2, xbuf, xbuf, TOK, DIM, UPD, nullptr, nullptr, nullptr);

    // ---- block 4: expert MLP ----
    ln_stats_kernel<<<(TOK * 32 + 255) / 256, 256>>>(xbuf, p_st);
    gemm_tf32_kernel<2, 1><<<gemm_grid128(TOK, MLP2), 256>>>(
        xbuf, emlp_w1, emlp_b1, nullptr, p_big, TOK, MLP2, DIM, p_st, eln2_g, eln2_b);
    gemm_tf32_kernel<3, 0><<<gemm_grid128(TOK, DIM), 256>>>(
        p_big, emlp_w2, emlp_b2, xbuf, xbuf, TOK, DIM, MLP2, nullptr, nullptr, nullptr);
}

// round 16
// speedup vs baseline: 1.4542x; 1.0489x over previous
#include <cuda_runtime.h>
#include <math.h>

#define BSZn 32
#define SEQ 243
#define DIM 544
#define NH 8
#define HDIM 68
#define NSEED 17
#define UPD 1088
#define UC 136
#define MLP1 2176
#define MLP2 1088
#define TOK (BSZn*SEQ)          /* 7776 */
#define BHN (BSZn*NH*SEQ)       /* 62208 */

// ---------------- scratch (static device globals; no allocation) ----------------
__device__ float g_qkv[TOK*3*DIM];      // qkv, later xu
__device__ float g_o[TOK*DIM];          // attention output
__device__ float g_big[TOK*MLP1];       // mlp hidden / o2 / emlp hidden
__device__ float g_a[BHN*NSEED];        // expert attention weights
__device__ float g_s0[NSEED*UPD];
__device__ float g_s1[NSEED*UPD];
__device__ float g_mean[NSEED];
__device__ float g_stats[TOK*2];        // per-token LN (mean, inv)

// ---------------- LN stats: warp per token ----------------
__global__ void ln_stats_kernel(const float* __restrict__ x, float* __restrict__ stats) {
    const int warp = (blockIdx.x * blockDim.x + threadIdx.x) >> 5;
    if (warp >= TOK) return;
    const int lane = threadIdx.x & 31;
    const float* xr = x + (size_t)warp * DIM;
    float s = 0.f, s2 = 0.f;
#pragma unroll
    for (int i = 0; i < 17; i++) {          // 544 = 32*17 exact
        float v = xr[lane + 32 * i];
        s += v; s2 += v * v;
    }
#pragma unroll
    for (int off = 16; off; off >>= 1) {
        s  += __shfl_xor_sync(~0u, s,  off);
        s2 += __shfl_xor_sync(~0u, s2, off);
    }
    if (lane == 0) {
        float mean = s * (1.f / (float)DIM);
        float var  = s2 * (1.f / (float)DIM) - mean * mean;
        stats[2 * warp]     = mean;
        stats[2 * warp + 1] = rsqrtf(var + 1e-5f);
    }
}

// ======================= tf32 tensor-core GEMM =======================
// C[M,N] = op(A)[M,K] * B[N,K]^T (+epilogue). K % 32 == 0.
// Block tile 128 x BN x 32, 256 threads. BN=128: warp tile 32x64. BN=64: warp tile 32x32.
// LNA=1: A element -> (a - mean_row)*inv_row*g[col] + b[col]  (fused LayerNorm)
// EPI: 0 none, 1 +bias, 2 +bias+GELU(exact), 3 +bias+residual

__device__ __forceinline__ unsigned cvt_tf32(float x) {
    unsigned u;
    asm("cvt.rna.tf32.f32 %0, %1;" : "=r"(u) : "f"(x));
    return u;
}

__device__ __forceinline__ void mma_tf32(float* d, const unsigned* a, unsigned b0, unsigned b1) {
    asm volatile("mma.sync.aligned.m16n8k8.row.col.f32.tf32.tf32.f32 "
                 "{%0,%1,%2,%3}, {%4,%5,%6,%7}, {%8,%9}, {%0,%1,%2,%3};\n"
                 : "+f"(d[0]), "+f"(d[1]), "+f"(d[2]), "+f"(d[3])
                 : "r"(a[0]), "r"(a[1]), "r"(a[2]), "r"(a[3]), "r"(b0), "r"(b1));
}

template<int EPI, int LNA, int BN>
__global__ __launch_bounds__(256, 2)
void gemm_tf32_kernel(const float* __restrict__ A, const float* __restrict__ B,
                      const float* __restrict__ bias, const float* __restrict__ res,
                      float* __restrict__ C, int M, int Nn, int K,
                      const float* __restrict__ lnstats,
                      const float* __restrict__ lng, const float* __restrict__ lnb) {
    __shared__ unsigned As[128 * 36];   // [row][k], pad 36 -> conflict-free frag loads
    __shared__ unsigned Bs[BN * 36];    // [col(n)][k]
    constexpr int NT = BN / 16;         // n-subtiles per warp (warp tile N = BN/2)
    constexpr int BP = BN / 32;         // B staging groups (32 rows each)

    const int tid  = threadIdx.x;
    const int warp = tid >> 5, lane = tid & 31;
    const int wm = (warp >> 1) * 32;    // warp row base (4 warps along M)
    const int wn = (warp & 1) * (BN / 2); // warp col base (2 warps along N)
    const int q  = lane & 3;            // k quad
    const int rg = lane >> 2;           // row/col group 0..7
    const int m0 = blockIdx.y * 128, n0 = blockIdx.x * BN;

    // staging map: each thread loads float4 rows stride 32
    const int lr = tid >> 3;            // base row 0..31 (stride 32)
    const int lc = (tid & 7) * 4;       // k offset 0..28

    float4 ra[4], rb[BP];
    float acc[2][NT][4];
#pragma unroll
    for (int i = 0; i < 2; i++)
#pragma unroll
        for (int j = 0; j < NT; j++)
#pragma unroll
            for (int c = 0; c < 4; c++) acc[i][j][c] = 0.f;

    const int T = K >> 5;

    // load tile t into registers (optionally applying fused LayerNorm to A)
    auto load_t = [&](int t) {
        const int kb = t * 32 + lc;
        float4 g4, bb4;
        if (LNA) {
            g4  = *(const float4*)(lng + kb);
            bb4 = *(const float4*)(lnb + kb);
        }
#pragma unroll
        for (int p = 0; p < 4; p++) {
            int r = lr + p * 32;
            int ar = m0 + r;
            if (ar < M) {
                float4 v = *(const float4*)(A + (size_t)ar * K + kb);
                if (LNA) {
                    float2 st = *(const float2*)(lnstats + 2 * ar);
                    v.x = (v.x - st.x) * st.y * g4.x + bb4.x;
                    v.y = (v.y - st.x) * st.y * g4.y + bb4.y;
                    v.z = (v.z - st.x) * st.y * g4.z + bb4.z;
                    v.w = (v.w - st.x) * st.y * g4.w + bb4.w;
                }
                ra[p] = v;
            } else ra[p] = make_float4(0.f, 0.f, 0.f, 0.f);
        }
#pragma unroll
        for (int p = 0; p < BP; p++) {
            int br = n0 + lr + p * 32;
            rb[p] = (br < Nn) ? *(const float4*)(B + (size_t)br * K + kb)
                              : make_float4(0.f, 0.f, 0.f, 0.f);
        }
    };
    // convert + store registers into smem
    auto store_t = [&]() {
#pragma unroll
        for (int p = 0; p < 4; p++) {
            int r = lr + p * 32;
            unsigned* da = &As[r * 36 + lc];
            da[0] = cvt_tf32(ra[p].x); da[1] = cvt_tf32(ra[p].y);
            da[2] = cvt_tf32(ra[p].z); da[3] = cvt_tf32(ra[p].w);
        }
#pragma unroll
        for (int p = 0; p < BP; p++) {
            int r = lr + p * 32;
            unsigned* db = &Bs[r * 36 + lc];
            db[0] = cvt_tf32(rb[p].x); db[1] = cvt_tf32(rb[p].y);
            db[2] = cvt_tf32(rb[p].z); db[3] = cvt_tf32(rb[p].w);
        }
    };

    load_t(0);
    store_t();
    __syncthreads();

    for (int t = 0; t < T; t++) {
        if (t + 1 < T) load_t(t + 1);   // global prefetch overlaps compute

#pragma unroll
        for (int s = 0; s < 4; s++) {
            const int k0 = s * 8;
            unsigned afr[2][4];
#pragma unroll
            for (int mt = 0; mt < 2; mt++) {
                int r = wm + mt * 16 + rg;
                afr[mt][0] = As[r * 36 + k0 + q];
                afr[mt][1] = As[(r + 8) * 36 + k0 + q];
                afr[mt][2] = As[r * 36 + k0 + q + 4];
                afr[mt][3] = As[(r + 8) * 36 + k0 + q + 4];
            }
#pragma unroll
            for (int nt = 0; nt < NT; nt++) {
                int cb = wn + nt * 8 + rg;
                unsigned b0 = Bs[cb * 36 + k0 + q];
                unsigned b1 = Bs[cb * 36 + k0 + q + 4];
                mma_tf32(acc[0][nt], afr[0], b0, b1);
                mma_tf32(acc[1][nt], afr[1], b0, b1);
            }
        }

        if (t + 1 < T) {
            __syncthreads();   // all warps done reading smem
            store_t();
            __syncthreads();   // stores visible
        }
    }

    // epilogue
#pragma unroll
    for (int mt = 0; mt < 2; mt++)
#pragma unroll
        for (int half = 0; half < 2; half++) {
            int row = m0 + wm + mt * 16 + rg + half * 8;
            if (row >= M) continue;
#pragma unroll
            for (int nt = 0; nt < NT; nt++) {
                int col = n0 + wn + nt * 8 + 2 * q;
                if (col >= Nn) continue;
                float v0 = acc[mt][nt][half * 2 + 0];
                float v1 = acc[mt][nt][half * 2 + 1];
                if (EPI >= 1) { v0 += bias[col]; v1 += bias[col + 1]; }
                if (EPI == 2) {
                    v0 = 0.5f * v0 * (1.0f + erff(v0 * 0.70710678118654752f));
                    v1 = 0.5f * v1 * (1.0f + erff(v1 * 0.70710678118654752f));
                }
                size_t idx = (size_t)row * Nn + col;
                if (EPI == 3) { v0 += res[idx]; v1 += res[idx + 1]; }
                C[idx] = v0; C[idx + 1] = v1;
            }
        }
}

// ---------------- batched seed GEMM (s0 & s1 in one launch, FFMA path) ----------------
__global__ void seed_gemm_kernel(const float* __restrict__ seed,
                                 const float* __restrict__ w0, const float* __restrict__ b0,
                                 const float* __restrict__ w1, const float* __restrict__ b1,
                                 float* __restrict__ s0out, float* __restrict__ s1out) {
    const float* B    = blockIdx.z ? w1 : w0;
    const float* bias = blockIdx.z ? b1 : b0;
    float*       C    = blockIdx.z ? s1out : s0out;
    const int M = NSEED, Nn = UPD, K = DIM;

    __shared__ float As[16][64];
    __shared__ float Bs[16][64];
    const int tid = threadIdx.x;
    const int n0 = blockIdx.x * 64;
    const int ty = tid >> 4;
    const int tx = tid & 15;
    const int lm = tid >> 2;
    const int lk = (tid & 3) * 4;

    float acc[4][4];
#pragma unroll
    for (int i = 0; i < 4; i++)
#pragma unroll
        for (int j = 0; j < 4; j++) acc[i][j] = 0.f;

    for (int k0 = 0; k0 < K; k0 += 16) {
        float4 a4 = make_float4(0.f, 0.f, 0.f, 0.f);
        if (lm < M) a4 = *(const float4*)(seed + (size_t)lm * K + k0 + lk);
        As[lk + 0][lm] = a4.x; As[lk + 1][lm] = a4.y;
        As[lk + 2][lm] = a4.z; As[lk + 3][lm] = a4.w;

        float4 b4 = make_float4(0.f, 0.f, 0.f, 0.f);
        int br = n0 + lm;
        if (br < Nn) b4 = *(const float4*)(B + (size_t)br * K + k0 + lk);
        Bs[lk + 0][lm] = b4.x; Bs[lk + 1][lm] = b4.y;
        Bs[lk + 2][lm] = b4.z; Bs[lk + 3][lm] = b4.w;
        __syncthreads();

#pragma unroll
        for (int kk = 0; kk < 16; kk++) {
            float4 av = *(const float4*)(&As[kk][ty * 4]);
            float4 bv = *(const float4*)(&Bs[kk][tx * 4]);
            float am[4] = {av.x, av.y, av.z, av.w};
            float bn[4] = {bv.x, bv.y, bv.z, bv.w};
#pragma unroll
            for (int i = 0; i < 4; i++)
#pragma unroll
                for (int j = 0; j < 4; j++) acc[i][j] = fmaf(am[i], bn[j], acc[i][j]);
        }
        __syncthreads();
    }

#pragma unroll
    for (int i = 0; i < 4; i++) {
        int row = ty * 4 + i;
        if (row >= M) continue;
#pragma unroll
        for (int j = 0; j < 4; j++) {
            int col = n0 + tx * 4 + j;
            if (col >= Nn) continue;
            C[(size_t)row * Nn + col] = acc[i][j] + bias[col];
        }
    }
}

// ---------------- Attention v4: block per (b,h), warp x 4 queries, K/V reuse ----------------
#define KPAD 76                        /* conflict-free pitch */
#define NW3 16                         /* warps per block */
#define IQ 4                           /* queries per warp pass */
#define PPITCH 244                     /* prob row pitch (mult of 4) */

__global__ __launch_bounds__(512)
void attn4_kernel(const float* __restrict__ qkv, const float* __restrict__ btab,
                  float* __restrict__ o) {
    extern __shared__ float sh[];
    float* k_sh    = sh;                           // [SEQ*KPAD]
    float* v_sh    = k_sh + SEQ * KPAD;            // [SEQ*KPAD]
    float* p_sh    = v_sh + SEQ * KPAD;            // [NW3*IQ*PPITCH]
    float* q_sh    = p_sh + NW3 * IQ * PPITCH;     // [NW3*IQ*HDIM]
    float* bias_sh = q_sh + NW3 * IQ * HDIM;       // [2*SEQ-1]

    const int bh = blockIdx.x;
    const int h = bh % NH;
    const int b = bh / NH;
    const int tid = threadIdx.x;
    const int lane = tid & 31, w = tid >> 5;

    // block preload: k, v, bias
    for (int idx = tid; idx < SEQ * HDIM; idx += 512) {
        int j = idx / HDIM, c = idx % HDIM;
        size_t base = ((size_t)(b * SEQ + j) * 3) * DIM + h * HDIM + c;
        k_sh[j * KPAD + c] = qkv[base + DIM];
        v_sh[j * KPAD + c] = qkv[base + 2 * DIM];
    }
    for (int idx = tid; idx < 2 * SEQ - 1; idx += 512)
        bias_sh[idx] = btab[h * (2 * SEQ - 1) + idx];
    __syncthreads();            // the only block barrier

    const float scale = rsqrtf((float)HDIM);
    float* q_w  = q_sh + w * IQ * HDIM;
    float* p_w0 = p_sh + w * IQ * PPITCH;

    int jj[8], koff[8];
#pragma unroll
    for (int t = 0; t < 8; t++) {
        int j = lane + 32 * t;
        jj[t] = j;
        koff[t] = (j < SEQ ? j : SEQ - 1) * KPAD;
    }

    const int c2 = 2 * lane;
    const bool xtra = (lane < 2);
    const int cx = 64 + 2 * lane;

    for (int g = w; g * IQ < SEQ; g += NW3) {
        const int i0 = g * IQ;

        // warp-private q tile load (each query read once per block total)
        for (int idx = lane; idx < IQ * HDIM; idx += 32) {
            int qi = idx / HDIM, c = idx - qi * HDIM;
            int i = i0 + qi;
            q_w[idx] = (i < SEQ) ? qkv[((size_t)(b * SEQ + i) * 3) * DIM + h * HDIM + c] : 0.f;
        }
        __syncwarp();

        // ---- scores: k4 loads shared across IQ queries ----
        float sc[IQ][8];
#pragma unroll
        for (int qi = 0; qi < IQ; qi++)
#pragma unroll
            for (int t = 0; t < 8; t++) sc[qi][t] = 0.f;

#pragma unroll
        for (int c4 = 0; c4 < HDIM / 4; c4++) {
            float4 q4[IQ];
#pragma unroll
            for (int qi = 0; qi < IQ; qi++)
                q4[qi] = ((const float4*)(q_w + qi * HDIM))[c4];
#pragma unroll
            for (int t = 0; t < 8; t++) {
                float4 k4 = *(const float4*)(k_sh + koff[t] + 4 * c4);
#pragma unroll
                for (int qi = 0; qi < IQ; qi++) {
                    sc[qi][t] = fmaf(q4[qi].x, k4.x, sc[qi][t]);
                    sc[qi][t] = fmaf(q4[qi].y, k4.y, sc[qi][t]);
                    sc[qi][t] = fmaf(q4[qi].z, k4.z, sc[qi][t]);
                    sc[qi][t] = fmaf(q4[qi].w, k4.w, sc[qi][t]);
                }
            }
        }

        // ---- per-query softmax (warp shuffles) + prob writes ----
#pragma unroll
        for (int qi = 0; qi < IQ; qi++) {
            const int i = i0 + qi;
            const bool qv = (i < SEQ);
            float* p_w = p_w0 + qi * PPITCH;
            float mx = -1e30f;
#pragma unroll
            for (int t = 0; t < 8; t++) {
                if (qv && jj[t] < SEQ) {
                    sc[qi][t] = sc[qi][t] * scale + bias_sh[i - jj[t] + SEQ - 1];
                    mx = fmaxf(mx, sc[qi][t]);
                } else sc[qi][t] = -1e30f;
            }
#pragma unroll
            for (int off = 16; off; off >>= 1) mx = fmaxf(mx, __shfl_xor_sync(~0u, mx, off));
            float sum = 0.f;
#pragma unroll
            for (int t = 0; t < 8; t++) {
                float e = (qv && jj[t] < SEQ) ? __expf(sc[qi][t] - mx) : 0.f;
                sc[qi][t] = e;
                sum += e;
            }
#pragma unroll
            for (int off = 16; off; off >>= 1) sum += __shfl_xor_sync(~0u, sum, off);
            const float invS = qv ? (1.f / sum) : 0.f;
#pragma unroll
            for (int t = 0; t < 8; t++)
                if (jj[t] < PPITCH) p_w[jj[t]] = sc[qi][t] * invS;   // j=243 gets 0
        }
        __syncwarp();

        // ---- PV: v2 loads shared across IQ queries, probs as float4 broadcast ----
        float acc[IQ][2], accx[IQ][2];
#pragma unroll
        for (int qi = 0; qi < IQ; qi++) {
            acc[qi][0] = acc[qi][1] = 0.f;
            accx[qi][0] = accx[qi][1] = 0.f;
        }

#define PV_STEP(COMP, JOFF)                                                    \
        {                                                                      \
            const float* vrow = v_sh + (j4 + (JOFF)) * KPAD;                   \
            float2 v2 = *(const float2*)(vrow + c2);                           \
            _Pragma("unroll")                                                  \
            for (int qi = 0; qi < IQ; qi++) {                                  \
                acc[qi][0] = fmaf(P[qi].COMP, v2.x, acc[qi][0]);               \
                acc[qi][1] = fmaf(P[qi].COMP, v2.y, acc[qi][1]);               \
            }                                                                  \
            if (xtra) {                                                        \
                float2 vx = *(const float2*)(vrow + cx);                       \
                _Pragma("unroll")                                              \
                for (int qi = 0; qi < IQ; qi++) {                              \
                    accx[qi][0] = fmaf(P[qi].COMP, vx.x, accx[qi][0]);         \
                    accx[qi][1] = fmaf(P[qi].COMP, vx.y, accx[qi][1]);         \
                }                                                              \
            }                                                                  \
        }

#pragma unroll 1
        for (int j4 = 0; j4 < 240; j4 += 4) {
            float4 P[IQ];
#pragma unroll
            for (int qi = 0; qi < IQ; qi++)
                P[qi] = *(const float4*)(p_w0 + qi * PPITCH + j4);
            PV_STEP(x, 0)
            PV_STEP(y, 1)
            PV_STEP(z, 2)
            PV_STEP(w, 3)
        }
        // tail j = 240..242
        for (int j = 240; j < SEQ; j++) {
            const float* vrow = v_sh + j * KPAD;
            float2 v2 = *(const float2*)(vrow + c2);
#pragma unroll
            for (int qi = 0; qi < IQ; qi++) {
                float p = p_w0[qi * PPITCH + j];
                acc[qi][0] = fmaf(p, v2.x, acc[qi][0]);
                acc[qi][1] = fmaf(p, v2.y, acc[qi][1]);
            }
            if (xtra) {
                float2 vx = *(const float2*)(vrow + cx);
#pragma unroll
                for (int qi = 0; qi < IQ; qi++) {
                    float p = p_w0[qi * PPITCH + j];
                    accx[qi][0] = fmaf(p, vx.x, accx[qi][0]);
                    accx[qi][1] = fmaf(p, vx.y, accx[qi][1]);
                }
            }
        }
#undef PV_STEP

        // ---- write outputs ----
#pragma unroll
        for (int qi = 0; qi < IQ; qi++) {
            int i = i0 + qi;
            if (i >= SEQ) break;
            float* orow = o + (size_t)(b * SEQ + i) * DIM + h * HDIM;
            orow[c2] = acc[qi][0];
            orow[c2 + 1] = acc[qi][1];
            if (xtra) { orow[cx] = accx[qi][0]; orow[cx + 1] = accx[qi][1]; }
        }
        __syncwarp();
    }
}

#define ATTN4_SMEM ((2*SEQ*KPAD + NW3*IQ*PPITCH + NW3*IQ*HDIM + (2*SEQ-1)) * (int)sizeof(float))

// ---------------- expert logits: warp per (b,h,f) ----------------
__global__ void expert_logits_kernel(const float* __restrict__ xu, const float* __restrict__ s0,
                                     float* __restrict__ a) {
    const int gw = (blockIdx.x * blockDim.x + threadIdx.x) >> 5;
    if (gw >= BHN) return;
    const int lane = threadIdx.x & 31;
    const int f = gw % SEQ;
    const int h = (gw / SEQ) % NH;
    const int b = gw / (SEQ * NH);
    const float* xr = xu + (size_t)(b * SEQ + f) * UPD + h * UC;
    float xv[5];
#pragma unroll
    for (int q = 0; q < 5; q++) { int c = lane + 32 * q; xv[q] = (c < UC) ? xr[c] : 0.f; }
    const float* s0h = s0 + h * UC;
    float* ar = a + (size_t)gw * NSEED;
    for (int n = 0; n < NSEED; n++) {
        const float* sr = s0h + (size_t)n * UPD;
        float p = 0.f;
#pragma unroll
        for (int q = 0; q < 5; q++) { int c = lane + 32 * q; if (c < UC) p += xv[q] * sr[c]; }
        for (int off = 16; off; off >>= 1) p += __shfl_xor_sync(~0u, p, off);
        if (lane == 0) ar[n] = p;
    }
}

// ---------------- softmax over f (axis=-2): block per (b,h,n) ----------------
__global__ void softmax_f_kernel(float* __restrict__ a) {
    const int idx = blockIdx.x;            // b*H*NS + h*NS + n
    const int n = idx % NSEED;
    const int bh = idx / NSEED;
    float* base = a + (size_t)bh * SEQ * NSEED + n;
    const int tid = threadIdx.x;           // 256
    __shared__ float redm[8], redsum[8], bcast[2];
    const int lane = tid & 31, w = tid >> 5;
    float v = (tid < SEQ) ? base[(size_t)tid * NSEED] : -1e30f;
    float m = v;
    for (int off = 16; off; off >>= 1) m = fmaxf(m, __shfl_xor_sync(~0u, m, off));
    if (lane == 0) redm[w] = m;
    __syncthreads();
    if (tid == 0) {
        float mm = redm[0];
        for (int k = 1; k < 8; k++) mm = fmaxf(mm, redm[k]);
        bcast[0] = mm;
    }
    __syncthreads();
    const float M = bcast[0];
    float e = (tid < SEQ) ? __expf(v - M) : 0.f;
    float s = e;
    for (int off = 16; off; off >>= 1) s += __shfl_xor_sync(~0u, s, off);
    if (lane == 0) redsum[w] = s;
    __syncthreads();
    if (tid == 0) {
        float ss = 0.f;
        for (int k = 0; k < 8; k++) ss += redsum[k];
        bcast[1] = 1.f / ss;
    }
    __syncthreads();
    if (tid < SEQ) base[(size_t)tid * NSEED] = e * bcast[1];
}

// ---------------- normalize over n, accumulate mean, produce o2 ----------------
__global__ void expert_out_kernel(const float* __restrict__ a, const float* __restrict__ s1,
                                  float* __restrict__ o2, float* __restrict__ mean_acc) {
    const int gw = blockIdx.x;             // (b,h,f)
    const int f = gw % SEQ;
    const int h = (gw / SEQ) % NH;
    const int b = gw / (SEQ * NH);
    __shared__ float a_sh[NSEED];
    __shared__ float inv_s;
    const int tid = threadIdx.x;           // 160
    if (tid < NSEED) a_sh[tid] = a[(size_t)gw * NSEED + tid];
    __syncthreads();
    if (tid == 0) {
        float s = 0.f;
        for (int n = 0; n < NSEED; n++) s += a_sh[n];
        inv_s = 1.f / (1e-7f + s);
    }
    __syncthreads();
    if (tid < NSEED) {
        float val = a_sh[tid] * inv_s;
        a_sh[tid] = val;
        atomicAdd(mean_acc + tid, val);
    }
    __syncthreads();
    if (tid < UC) {
        const float* s1h = s1 + h * UC + tid;
        float acc = 0.f;
#pragma unroll
        for (int n = 0; n < NSEED; n++) acc += a_sh[n] * s1h[(size_t)n * UPD];
        o2[(size_t)(b * SEQ + f) * UPD + h * UC + tid] = acc;
    }
}

__global__ void zero_mean_kernel(float* __restrict__ mean_acc) {
    if (threadIdx.x < NSEED) mean_acc[threadIdx.x] = 0.f;
}

__global__ void finalize_mean_kernel(const float* __restrict__ mean_acc, float* __restrict__ out) {
    if (threadIdx.x < NSEED)
        out[threadIdx.x] = mean_acc[threadIdx.x] * (1.0f / (float)BHN);
}

// ---------------- driver ----------------
static inline dim3 gemm_grid(int M, int Nn, int BN) { return dim3((Nn + BN - 1) / BN, (M + 127) / 128); }

extern "C" void kernel_launch(void* const* d_in, const int* in_sizes, int n_in,
                              void* d_out, int out_size) {
    const float* x      = (const float*)d_in[0];
    const float* seed   = (const float*)d_in[1];
    const float* ln1_g  = (const float*)d_in[2];
    const float* ln1_b  = (const float*)d_in[3];
    const float* w_qkv  = (const float*)d_in[4];
    const float* w_proj = (const float*)d_in[5];
    const float* b_proj = (const float*)d_in[6];
    const float* b_tab  = (const float*)d_in[7];
    const float* ln2_g  = (const float*)d_in[8];
    const float* ln2_b  = (const float*)d_in[9];
    const float* mlp_w1 = (const float*)d_in[10];
    const float* mlp_b1 = (const float*)d_in[11];
    const float* mlp_w2 = (const float*)d_in[12];
    const float* mlp_b2 = (const float*)d_in[13];
    const float* eln1_g = (const float*)d_in[14];
    const float* eln1_b = (const float*)d_in[15];
    const float* w_trans= (const float*)d_in[16];
    const float* b_trans= (const float*)d_in[17];
    const float* w0     = (const float*)d_in[18];
    const float* b0     = (const float*)d_in[19];
    const float* w1     = (const float*)d_in[20];
    const float* b1     = (const float*)d_in[21];
    const float* w_proj2= (const float*)d_in[22];
    const float* b_proj2= (const float*)d_in[23];
    const float* eln2_g = (const float*)d_in[24];
    const float* eln2_b = (const float*)d_in[25];
    const float* emlp_w1= (const float*)d_in[26];
    const float* emlp_b1= (const float*)d_in[27];
    const float* emlp_w2= (const float*)d_in[28];
    const float* emlp_b2= (const float*)d_in[29];

    float* xbuf = (float*)d_out;                  // running x lives in d_out
    float* out_mean = (float*)d_out + (size_t)TOK * DIM;

    float *p_qkv, *p_o, *p_big, *p_a, *p_s0, *p_s1, *p_mean, *p_st;
    cudaGetSymbolAddress((void**)&p_qkv, g_qkv);
    cudaGetSymbolAddress((void**)&p_o,   g_o);
    cudaGetSymbolAddress((void**)&p_big, g_big);
    cudaGetSymbolAddress((void**)&p_a,   g_a);
    cudaGetSymbolAddress((void**)&p_s0,  g_s0);
    cudaGetSymbolAddress((void**)&p_s1,  g_s1);
    cudaGetSymbolAddress((void**)&p_mean,g_mean);
    cudaGetSymbolAddress((void**)&p_st,  g_stats);

    cudaFuncSetAttribute(attn4_kernel, cudaFuncAttributeMaxDynamicSharedMemorySize, ATTN4_SMEM);

    zero_mean_kernel<<<1, 32>>>(p_mean);

    // ---- block 1: attention (LN fused into qkv GEMM; residual reads original x) ----
    ln_stats_kernel<<<(TOK * 32 + 255) / 256, 256>>>(x, p_st);
    gemm_tf32_kernel<0, 1, 128><<<gemm_grid(TOK, 3 * DIM, 128), 256>>>(
        x, w_qkv, nullptr, nullptr, p_qkv, TOK, 3 * DIM, DIM, p_st, ln1_g, ln1_b);
    attn4_kernel<<<BSZn * NH, 512, ATTN4_SMEM>>>(p_qkv, b_tab, p_o);
    gemm_tf32_kernel<3, 0, 64><<<gemm_grid(TOK, DIM, 64), 256>>>(
        p_o, w_proj, b_proj, x, xbuf, TOK, DIM, DIM, nullptr, nullptr, nullptr);

    // ---- block 2: MLP ----
    ln_stats_kernel<<<(TOK * 32 + 255) / 256, 256>>>(xbuf, p_st);
    gemm_tf32_kernel<2, 1, 128><<<gemm_grid(TOK, MLP1, 128), 256>>>(
        xbuf, mlp_w1, mlp_b1, nullptr, p_big, TOK, MLP1, DIM, p_st, ln2_g, ln2_b);
    gemm_tf32_kernel<3, 0, 64><<<gemm_grid(TOK, DIM, 64), 256>>>(
        p_big, mlp_w2, mlp_b2, xbuf, xbuf, TOK, DIM, MLP1, nullptr, nullptr, nullptr);

    // ---- block 3: seed-expert attention ----
    ln_stats_kernel<<<(TOK * 32 + 255) / 256, 256>>>(xbuf, p_st);
    gemm_tf32_kernel<1, 1, 128><<<gemm_grid(TOK, UPD, 128), 256>>>(
        xbuf, w_trans, b_trans, nullptr, p_qkv, TOK, UPD, DIM, p_st, eln1_g, eln1_b);
    seed_gemm_kernel<<<dim3(UPD / 64, 1, 2), 256>>>(seed, w0, b0, w1, b1, p_s0, p_s1);
    expert_logits_kernel<<<(BHN * 32 + 127) / 128, 128>>>(p_qkv, p_s0, p_a);
    softmax_f_kernel<<<BSZn * NH * NSEED, 256>>>(p_a);
    expert_out_kernel<<<BHN, 160>>>(p_a, p_s1, p_big, p_mean);
    finalize_mean_kernel<<<1, 32>>>(p_mean, out_mean);
    gemm_tf32_kernel<3, 0, 64><<<gemm_grid(TOK, DIM, 64), 256>>>(
        p_big, w_proj2, b_proj2, xbuf, xbuf, TOK, DIM, UPD, nullptr, nullptr, nullptr);

    // ---- block 4: expert MLP ----
    ln_stats_kernel<<<(TOK * 32 + 255) / 256, 256>>>(xbuf, p_st);
    gemm_tf32_kernel<2, 1, 128><<<gemm_grid(TOK, MLP2, 128), 256>>>(
        xbuf, emlp_w1, emlp_b1, nullptr, p_big, TOK, MLP2, DIM, p_st, eln2_g, eln2_b);
    gemm_tf32_kernel<3, 0, 64><<<gemm_grid(TOK, DIM, 64), 256>>>(
        p_big, emlp_w2, emlp_b2, xbuf, xbuf, TOK, DIM, MLP2, nullptr, nullptr, nullptr);
}